// round 11
// baseline (speedup 1.0000x reference)
#include <cuda_runtime.h>
#include <cuda_bf16.h>
#include <math.h>
#include <stdint.h>

#define BB    32
#define TTEXT 400
#define TMEL  1600
#define ADIM  384
#define ODIM  80
#define CIPM  128   // mel input channels padded 80 -> 128

// ---------------- static scratch (no allocations allowed) ----------------
__device__ __nv_bfloat16 g_xht[(size_t)BB * TTEXT * ADIM];   // text conv2 out hi (attn H hi)
__device__ __nv_bfloat16 g_xlt[(size_t)BB * TTEXT * ADIM];   // text conv2 out lo (attn H lo)
__device__ __nv_bfloat16 g_xin[(size_t)BB * TTEXT * ADIM];   // text input hi
__device__ __nv_bfloat16 g_h1h[(size_t)BB * TTEXT * ADIM];
__device__ __nv_bfloat16 g_xhm[(size_t)BB * TMEL * CIPM];    // mel input hi (padded)
__device__ __nv_bfloat16 g_y1h[(size_t)BB * TMEL * ADIM];
__device__ __nv_bfloat16 g_y2h[(size_t)BB * TMEL * ADIM];
// weights bf16 hi/lo, layout [k][co][ci_padded]
__device__ __nv_bfloat16 g_wt1h[3 * 384 * ADIM], g_wt1l[3 * 384 * ADIM];
__device__ __nv_bfloat16 g_wt2h[1 * 384 * ADIM], g_wt2l[1 * 384 * ADIM];
__device__ __nv_bfloat16 g_wm1h[3 * 384 * CIPM], g_wm1l[3 * 384 * CIPM];
__device__ __nv_bfloat16 g_wm2h[3 * 384 * ADIM], g_wm2l[3 * 384 * ADIM];
__device__ __nv_bfloat16 g_wm3h[1 * 384 * ADIM], g_wm3l[1 * 384 * ADIM];
__device__ float g_hn[BB * TTEXT];
__device__ float g_yn[BB * TMEL];

// ---------------- PTX helpers (family-level only) ----------------
__device__ __forceinline__ unsigned int sm_u32(const void* p)
{
    return (unsigned int)__cvta_generic_to_shared(p);
}
__device__ __forceinline__ void cp16(unsigned int dst, const void* src,
                                     unsigned int bytes)
{
    asm volatile("cp.async.cg.shared.global [%0], [%1], 16, %2;"
                 :: "r"(dst), "l"(src), "r"(bytes) : "memory");
}
__device__ __forceinline__ void cp_commit()
{
    asm volatile("cp.async.commit_group;" ::: "memory");
}
template<int N>
__device__ __forceinline__ void cp_wait()
{
    asm volatile("cp.async.wait_group %0;" :: "n"(N) : "memory");
}
__device__ __forceinline__ void ldsm4(unsigned int* r, unsigned int addr)
{
    asm volatile("ldmatrix.sync.aligned.m8n8.x4.shared.b16 {%0,%1,%2,%3}, [%4];"
                 : "=r"(r[0]), "=r"(r[1]), "=r"(r[2]), "=r"(r[3]) : "r"(addr));
}
__device__ __forceinline__ void mma16816(float* c, const unsigned int* a,
                                         const unsigned int* b)
{
    asm volatile("mma.sync.aligned.m16n8k16.row.col.f32.bf16.bf16.f32 "
                 "{%0,%1,%2,%3}, {%4,%5,%6,%7}, {%8,%9}, {%0,%1,%2,%3};"
                 : "+f"(c[0]), "+f"(c[1]), "+f"(c[2]), "+f"(c[3])
                 : "r"(a[0]), "r"(a[1]), "r"(a[2]), "r"(a[3]),
                   "r"(b[0]), "r"(b[1]));
}
__device__ __forceinline__ unsigned int sw64(unsigned int bo)
{
    return bo ^ ((bo >> 3) & 0x30);
}

// ---------------- merged input split: hi only (A-side operands) ----------------
__global__ void xsplit_all_k(const float* __restrict__ hs, const float* __restrict__ ys,
                             __nv_bfloat16* __restrict__ xin, __nv_bfloat16* __restrict__ xhm)
{
    long idx = (long)blockIdx.x * 256 + threadIdx.x;
    if (blockIdx.y == 0) {
        long total = (long)BB * TTEXT * ADIM;
        if (idx >= total) return;
        xin[idx] = __float2bfloat16(hs[idx]);
    } else {
        long total = (long)BB * TMEL * CIPM;
        if (idx >= total) return;
        long r = idx >> 7;
        int  c = (int)(idx & 127);
        xhm[idx] = __float2bfloat16((c < ODIM) ? ys[r * ODIM + c] : 0.f);
    }
}

// ---------------- merged weight split: all 5 tensors (hi+lo, B-side) -------------
__device__ __forceinline__ void wsplit_one(const float* W, __nv_bfloat16* Wh,
                                           __nv_bfloat16* Wl, int CIN, int CIP,
                                           int KS, int idx)
{
    int total = KS * 384 * CIP;
    if (idx >= total) return;
    int k   = idx / (384 * CIP);
    int rem = idx - k * 384 * CIP;
    int co  = rem / CIP;
    int ci  = rem - co * CIP;
    float v = (ci < CIN) ? W[((size_t)co * CIN + ci) * KS + k] : 0.f;
    __nv_bfloat16 h = __float2bfloat16(v);
    Wh[idx] = h;
    Wl[idx] = __float2bfloat16(v - __bfloat162float(h));
}

__global__ void wsplit_all_k(const float* tw1, const float* tw2, const float* mw1,
                             const float* mw2, const float* mw3,
                             __nv_bfloat16* wt1h, __nv_bfloat16* wt1l,
                             __nv_bfloat16* wt2h, __nv_bfloat16* wt2l,
                             __nv_bfloat16* wm1h, __nv_bfloat16* wm1l,
                             __nv_bfloat16* wm2h, __nv_bfloat16* wm2l,
                             __nv_bfloat16* wm3h, __nv_bfloat16* wm3l)
{
    int idx = blockIdx.x * 256 + threadIdx.x;
    switch (blockIdx.y) {
    case 0: wsplit_one(tw1, wt1h, wt1l, ADIM, ADIM, 3, idx); break;
    case 1: wsplit_one(tw2, wt2h, wt2l, ADIM, ADIM, 1, idx); break;
    case 2: wsplit_one(mw1, wm1h, wm1l, ODIM, CIPM, 3, idx); break;
    case 3: wsplit_one(mw2, wm2h, wm2l, ADIM, ADIM, 3, idx); break;
    case 4: wsplit_one(mw3, wm3h, wm3l, ADIM, ADIM, 1, idx); break;
    }
}

// ---------------- conv1d via mma.sync, 2-term compensation (Ah*Bh + Ah*Bl) ------
// CTA tile: 128 time-rows x 128 couts. 8 warps, warp tile 64x32 (wm 2 x wn 4).
// 3-stage cp.async pipeline, single __syncthreads per K-step.
// Stage = Ah(8K)+Bh(8K)+Bl(8K) = 24KB; 3 stages + bias = 73KB -> 2 CTAs/SM.
#define CONV_SMEM (1024 + 3 * 24576)
template<int KS, int CIP, bool RELU, bool SPLITLO>
__global__ __launch_bounds__(256, 2)
void convmma_k(const __nv_bfloat16* __restrict__ Xh,
               const __nv_bfloat16* __restrict__ Wh, const __nv_bfloat16* __restrict__ Wl,
               const float* __restrict__ bias,
               __nv_bfloat16* __restrict__ Oh, __nv_bfloat16* __restrict__ Ol, int T)
{
    constexpr int PAD = (KS - 1) / 2;
    constexpr int NC  = CIP / 32;
    constexpr int NS  = KS * NC;
    extern __shared__ char smem[];
    const unsigned int su = sm_u32(smem);

    const int tid  = threadIdx.x;
    const int lane = tid & 31;
    const int wid  = tid >> 5;
    const int wm   = wid & 1;       // 2 groups of 64 time-rows
    const int wn   = wid >> 1;      // 4 groups of 32 couts
    const int b    = blockIdx.z;
    const int t0   = blockIdx.x * 128;
    const int n0   = blockIdx.y * 128;

    float* sBias = (float*)smem;
    if (tid < 128) sBias[tid] = bias[n0 + tid];

    const int g  = lane >> 3, wi = lane & 7;
    const int arow = ((g & 1) << 3) + wi, acg = g >> 1;
    const int brow = ((g >> 1) << 3) + wi, bcg = g & 1;

    // stage layout: Ah @0 (8KB), Bh @8192 (8KB), Bl @16384 (8KB)
    auto fill = [&](int step) {
        int s  = step % 3;
        int k  = step / NC;
        int ch = step - k * NC;
        unsigned int st = su + 1024 + s * 24576;
        // A: 128 rows x 4 chunks = 512 tasks
        #pragma unroll
        for (int i = tid; i < 512; i += 256) {
            int r = i >> 2, c = i & 3;
            unsigned int sw = sw64(r * 64 + c * 16);
            int t  = t0 + r + k - PAD;
            int tc = t < 0 ? 0 : (t >= T ? T - 1 : t);
            unsigned int ok = (t >= 0 && t < T) ? 16u : 0u;
            size_t src = ((size_t)b * T + tc) * CIP + ch * 32 + c * 8;
            cp16(st + sw, Xh + src, ok);
        }
        // B: 128 rows x 4 chunks x {hi,lo} = 1024 tasks
        #pragma unroll
        for (int i = tid; i < 1024; i += 256) {
            int tensor = i >> 9;
            int rem = i & 511;
            int r = rem >> 2, c = rem & 3;
            unsigned int sw = 8192 + sw64(r * 64 + c * 16) + tensor * 8192;
            size_t src = ((size_t)k * 384 + n0 + r) * CIP + ch * 32 + c * 8;
            cp16(st + sw, (tensor ? Wl : Wh) + src, 16u);
        }
        cp_commit();
    };

    float acc[4][4][4];
    #pragma unroll
    for (int i = 0; i < 4; i++)
        #pragma unroll
        for (int j = 0; j < 4; j++)
            #pragma unroll
            for (int e = 0; e < 4; e++) acc[i][j][e] = 0.f;

    fill(0);
    if (NS > 1) fill(1);
    for (int step = 0; step < NS; step++) {
        if (step == NS - 1) cp_wait<0>();
        else                cp_wait<1>();
        __syncthreads();
        if (step + 2 < NS) fill(step + 2);

        unsigned int st = su + 1024 + (step % 3) * 24576;

        #pragma unroll
        for (int kq = 0; kq < 2; kq++) {
            unsigned int a_h[4][4], b_h[2][4], b_l[2][4];
            #pragma unroll
            for (int i = 0; i < 4; i++) {
                unsigned int bo = sw64((wm * 64 + i * 16 + arow) * 64
                                       + (kq * 2 + acg) * 16);
                ldsm4(a_h[i], st + bo);
            }
            #pragma unroll
            for (int p = 0; p < 2; p++) {
                unsigned int bo = sw64((wn * 32 + p * 16 + brow) * 64
                                       + (kq * 2 + bcg) * 16);
                ldsm4(b_h[p], st + 8192 + bo);
                ldsm4(b_l[p], st + 16384 + bo);
            }
            #pragma unroll
            for (int i = 0; i < 4; i++)
                #pragma unroll
                for (int j = 0; j < 4; j++) {
                    const unsigned int* bh2 = &b_h[j >> 1][(j & 1) * 2];
                    const unsigned int* bl2 = &b_l[j >> 1][(j & 1) * 2];
                    mma16816(acc[i][j], a_h[i], bh2);
                    mma16816(acc[i][j], a_h[i], bl2);
                }
        }
    }

    #pragma unroll
    for (int i = 0; i < 4; i++) {
        #pragma unroll
        for (int half = 0; half < 2; half++) {
            int t = t0 + wm * 64 + i * 16 + (lane >> 2) + half * 8;
            if (t >= T) continue;
            size_t base = ((size_t)b * T + t) * 384 + n0;
            #pragma unroll
            for (int j = 0; j < 4; j++) {
                int c = wn * 32 + j * 8 + (lane & 3) * 2;
                float v0 = acc[i][j][half * 2]     + sBias[c];
                float v1 = acc[i][j][half * 2 + 1] + sBias[c + 1];
                if (RELU) { v0 = fmaxf(v0, 0.f); v1 = fmaxf(v1, 0.f); }
                __nv_bfloat16 h0 = __float2bfloat16(v0);
                __nv_bfloat16 h1 = __float2bfloat16(v1);
                __nv_bfloat162 hp; hp.x = h0; hp.y = h1;
                *(__nv_bfloat162*)&Oh[base + c] = hp;
                if (SPLITLO) {
                    __nv_bfloat162 lp;
                    lp.x = __float2bfloat16(v0 - __bfloat162float(h0));
                    lp.y = __float2bfloat16(v1 - __bfloat162float(h1));
                    *(__nv_bfloat162*)&Ol[base + c] = lp;
                }
            }
        }
    }
}

// ---------------- row squared-norms (lo optional) over 384 features -------------
__global__ void rownorm2_k(const __nv_bfloat16* __restrict__ Xh,
                           const __nv_bfloat16* __restrict__ Xl,
                           float* __restrict__ Nrm)
{
    int row = blockIdx.x;
    const __nv_bfloat16* ph = Xh + (size_t)row * 384;
    const __nv_bfloat16* pl = Xl ? Xl + (size_t)row * 384 : nullptr;
    float s = 0.f;
    for (int i = threadIdx.x; i < 384; i += 128) {
        float v = __bfloat162float(ph[i]);
        if (pl) v += __bfloat162float(pl[i]);
        s += v * v;
    }
    #pragma unroll
    for (int o = 16; o > 0; o >>= 1) s += __shfl_xor_sync(0xffffffffu, s, o);
    __shared__ float ps[4];
    if ((threadIdx.x & 31) == 0) ps[threadIdx.x >> 5] = s;
    __syncthreads();
    if (threadIdx.x == 0) Nrm[row] = ps[0] + ps[1] + ps[2] + ps[3];
}

// ---------------- fused distance mma-GEMM + sqrt + mask + log_softmax --------
// 2-term compensation (Yh*Hh + Yh*Hl).
#define ATTN_STAGE 69120
#define ATTN_SMEM  (2112 + 2 * ATTN_STAGE)
__global__ __launch_bounds__(256)
void attnmma_k(const __nv_bfloat16* __restrict__ Yh,
               const __nv_bfloat16* __restrict__ Hh, const __nv_bfloat16* __restrict__ Hl,
               const float* __restrict__ Yn, const float* __restrict__ Hn,
               const unsigned char* __restrict__ mask, float* __restrict__ Out)
{
    constexpr int NSTEP = ADIM / 32;   // 12
    extern __shared__ char smem[];
    float* sHnM = (float*)smem;
    float* sRed = (float*)(smem + 1600);
    const unsigned int su = sm_u32(smem);

    const int tid  = threadIdx.x;
    const int lane = tid & 31;
    const int wid  = tid >> 5;
    const int wm   = wid & 3;
    const int wn   = wid >> 2;
    const int b    = blockIdx.y;
    const int m0   = blockIdx.x * 64;

    for (int i = tid; i < 400; i += 256)
        sHnM[i] = mask[b * TTEXT + i] ? __int_as_float(0x7f800000) : Hn[b * TTEXT + i];

    auto fill = [&](int step) {
        int s = step & 1;
        int kc = step * 32;
        unsigned int st = su + 2112 + s * ATTN_STAGE;
        #pragma unroll 2
        for (int i = tid; i < 1600; i += 256) {
            int n = i >> 2, q = i & 3;
            unsigned int dst = st + 5120 + (n * 20 + q * 4) * 4;
            size_t src = ((size_t)b * TTEXT + n) * ADIM + kc + q * 8;
            cp16(dst,         Hh + src, 16u);
            cp16(dst + 32000, Hl + src, 16u);
        }
        {
            int i = tid;
            int r = i >> 2, q = i & 3;
            unsigned int dst = st + (r * 20 + q * 4) * 4;
            size_t src = ((size_t)b * TMEL + m0 + r) * ADIM + kc + q * 8;
            cp16(dst, Yh + src, 16u);
        }
        cp_commit();
    };

    float acc[25][4];
    #pragma unroll
    for (int j = 0; j < 25; j++)
        #pragma unroll
        for (int e = 0; e < 4; e++) acc[j][e] = 0.f;

    const int r0 = lane >> 2;
    const int lw = lane & 3;

    fill(0);
    for (int step = 0; step < NSTEP; step++) {
        int s = step & 1;
        if (step + 1 < NSTEP) { fill(step + 1); cp_wait<1>(); }
        else                  { cp_wait<0>(); }
        __syncthreads();

        const unsigned int st = su + 2112 + s * ATTN_STAGE;
        const uint32_t* Ys_h = (const uint32_t*)(smem + (st - su));
        const uint32_t* Hs_h = Ys_h + 1280;
        const uint32_t* Hs_l = Hs_h + 8000;

        #pragma unroll
        for (int kq = 0; kq < 2; kq++) {
            const int w0 = kq * 8 + lw;
            unsigned int ah[4];
            {
                int ra = (wm * 16 + r0) * 20;
                int rb = (wm * 16 + r0 + 8) * 20;
                ah[0] = Ys_h[ra + w0];     ah[1] = Ys_h[rb + w0];
                ah[2] = Ys_h[ra + w0 + 4]; ah[3] = Ys_h[rb + w0 + 4];
            }
            #pragma unroll
            for (int j = 0; j < 25; j++) {
                int n = (wn * 200 + j * 8 + r0) * 20;
                unsigned int bh[2], bl[2];
                bh[0] = Hs_h[n + w0]; bh[1] = Hs_h[n + w0 + 4];
                bl[0] = Hs_l[n + w0]; bl[1] = Hs_l[n + w0 + 4];
                mma16816(acc[j], ah, bh);
                mma16816(acc[j], ah, bl);
            }
        }
        __syncthreads();
    }

    int mrow0 = m0 + wm * 16 + r0;
    float yn0 = Yn[b * TMEL + mrow0];
    float yn1 = Yn[b * TMEL + mrow0 + 8];

    #pragma unroll
    for (int j = 0; j < 25; j++) {
        int c = wn * 200 + j * 8 + lw * 2;
        float hn0 = sHnM[c], hn1 = sHnM[c + 1];
        acc[j][0] = -sqrtf(fmaxf(yn0 + hn0 - 2.f * acc[j][0], 1e-12f));
        acc[j][1] = -sqrtf(fmaxf(yn0 + hn1 - 2.f * acc[j][1], 1e-12f));
        acc[j][2] = -sqrtf(fmaxf(yn1 + hn0 - 2.f * acc[j][2], 1e-12f));
        acc[j][3] = -sqrtf(fmaxf(yn1 + hn1 - 2.f * acc[j][3], 1e-12f));
    }

    float mx0 = -INFINITY, mx1 = -INFINITY;
    #pragma unroll
    for (int j = 0; j < 25; j++) {
        mx0 = fmaxf(mx0, fmaxf(acc[j][0], acc[j][1]));
        mx1 = fmaxf(mx1, fmaxf(acc[j][2], acc[j][3]));
    }
    #pragma unroll
    for (int o = 1; o <= 2; o <<= 1) {
        mx0 = fmaxf(mx0, __shfl_xor_sync(0xffffffffu, mx0, o));
        mx1 = fmaxf(mx1, __shfl_xor_sync(0xffffffffu, mx1, o));
    }
    if (lw == 0) {
        sRed[(wm * 16 + r0) * 2 + wn]     = mx0;
        sRed[(wm * 16 + r0 + 8) * 2 + wn] = mx1;
    }
    __syncthreads();
    mx0 = fmaxf(sRed[(wm * 16 + r0) * 2],     sRed[(wm * 16 + r0) * 2 + 1]);
    mx1 = fmaxf(sRed[(wm * 16 + r0 + 8) * 2], sRed[(wm * 16 + r0 + 8) * 2 + 1]);
    __syncthreads();

    float sm0 = 0.f, sm1 = 0.f;
    #pragma unroll
    for (int j = 0; j < 25; j++) {
        sm0 += __expf(acc[j][0] - mx0) + __expf(acc[j][1] - mx0);
        sm1 += __expf(acc[j][2] - mx1) + __expf(acc[j][3] - mx1);
    }
    #pragma unroll
    for (int o = 1; o <= 2; o <<= 1) {
        sm0 += __shfl_xor_sync(0xffffffffu, sm0, o);
        sm1 += __shfl_xor_sync(0xffffffffu, sm1, o);
    }
    if (lw == 0) {
        sRed[(wm * 16 + r0) * 2 + wn]     = sm0;
        sRed[(wm * 16 + r0 + 8) * 2 + wn] = sm1;
    }
    __syncthreads();
    sm0 = sRed[(wm * 16 + r0) * 2]     + sRed[(wm * 16 + r0) * 2 + 1];
    sm1 = sRed[(wm * 16 + r0 + 8) * 2] + sRed[(wm * 16 + r0 + 8) * 2 + 1];
    float lse0 = mx0 + __logf(sm0);
    float lse1 = mx1 + __logf(sm1);

    float* o0 = Out + ((size_t)b * TMEL + mrow0) * TTEXT;
    float* o1 = Out + ((size_t)b * TMEL + mrow0 + 8) * TTEXT;
    #pragma unroll
    for (int j = 0; j < 25; j++) {
        int c = wn * 200 + j * 8 + lw * 2;
        *(float2*)&o0[c] = make_float2(acc[j][0] - lse0, acc[j][1] - lse0);
        *(float2*)&o1[c] = make_float2(acc[j][2] - lse1, acc[j][3] - lse1);
    }
}

// ---------------- launch ----------------
extern "C" void kernel_launch(void* const* d_in, const int* in_sizes, int n_in,
                              void* d_out, int out_size)
{
    const float* hs   = (const float*)d_in[0];
    const float* ys   = (const float*)d_in[1];
    const unsigned char* mask = (const unsigned char*)d_in[2];
    const float* t_w1 = (const float*)d_in[3];
    const float* t_b1 = (const float*)d_in[4];
    const float* t_w2 = (const float*)d_in[5];
    const float* t_b2 = (const float*)d_in[6];
    const float* m_w1 = (const float*)d_in[7];
    const float* m_b1 = (const float*)d_in[8];
    const float* m_w2 = (const float*)d_in[9];
    const float* m_b2 = (const float*)d_in[10];
    const float* m_w3 = (const float*)d_in[11];
    const float* m_b3 = (const float*)d_in[12];
    float* out = (float*)d_out;

    __nv_bfloat16 *xht, *xlt, *xin, *h1h, *xhm, *y1h, *y2h;
    __nv_bfloat16 *wt1h, *wt1l, *wt2h, *wt2l, *wm1h, *wm1l, *wm2h, *wm2l, *wm3h, *wm3l;
    float *hn, *yn;
    cudaGetSymbolAddress((void**)&xht, g_xht); cudaGetSymbolAddress((void**)&xlt, g_xlt);
    cudaGetSymbolAddress((void**)&xin, g_xin); cudaGetSymbolAddress((void**)&h1h, g_h1h);
    cudaGetSymbolAddress((void**)&xhm, g_xhm);
    cudaGetSymbolAddress((void**)&y1h, g_y1h); cudaGetSymbolAddress((void**)&y2h, g_y2h);
    cudaGetSymbolAddress((void**)&wt1h, g_wt1h); cudaGetSymbolAddress((void**)&wt1l, g_wt1l);
    cudaGetSymbolAddress((void**)&wt2h, g_wt2h); cudaGetSymbolAddress((void**)&wt2l, g_wt2l);
    cudaGetSymbolAddress((void**)&wm1h, g_wm1h); cudaGetSymbolAddress((void**)&wm1l, g_wm1l);
    cudaGetSymbolAddress((void**)&wm2h, g_wm2h); cudaGetSymbolAddress((void**)&wm2l, g_wm2l);
    cudaGetSymbolAddress((void**)&wm3h, g_wm3h); cudaGetSymbolAddress((void**)&wm3l, g_wm3l);
    cudaGetSymbolAddress((void**)&hn, g_hn);   cudaGetSymbolAddress((void**)&yn, g_yn);

    cudaFuncSetAttribute(convmma_k<3, 384, true,  false>,
                         cudaFuncAttributeMaxDynamicSharedMemorySize, CONV_SMEM);
    cudaFuncSetAttribute(convmma_k<1, 384, false, true >,
                         cudaFuncAttributeMaxDynamicSharedMemorySize, CONV_SMEM);
    cudaFuncSetAttribute(convmma_k<1, 384, false, false>,
                         cudaFuncAttributeMaxDynamicSharedMemorySize, CONV_SMEM);
    cudaFuncSetAttribute(convmma_k<3, 128, true,  false>,
                         cudaFuncAttributeMaxDynamicSharedMemorySize, CONV_SMEM);
    cudaFuncSetAttribute(attnmma_k,
                         cudaFuncAttributeMaxDynamicSharedMemorySize, ATTN_SMEM);

    // #0: merged input split (hi only)
    {
        long mel = (long)BB * TMEL * CIPM;
        dim3 g((unsigned)((mel + 255) / 256), 2);
        xsplit_all_k<<<g, 256>>>(hs, ys, xin, xhm);
    }
    // #1: merged weight split
    {
        dim3 g((3 * 384 * ADIM + 255) / 256, 5);
        wsplit_all_k<<<g, 256>>>(t_w1, t_w2, m_w1, m_w2, m_w3,
                                 wt1h, wt1l, wt2h, wt2l, wm1h, wm1l,
                                 wm2h, wm2l, wm3h, wm3l);
    }

    // #2-#3: text prenet (conv2 output feeds attn B side -> hi+lo)
    {
        dim3 g((TTEXT + 127) / 128, 3, BB);
        convmma_k<3, 384, true,  false><<<g, 256, CONV_SMEM>>>(
            xin, wt1h, wt1l, t_b1, h1h, nullptr, TTEXT);
        convmma_k<1, 384, false, true ><<<g, 256, CONV_SMEM>>>(
            h1h, wt2h, wt2l, t_b2, xht, xlt, TTEXT);
    }
    // #4-#6: mel prenet (#5 = mel conv2, the ncu-profiled launch)
    {
        dim3 g((TMEL + 127) / 128, 3, BB);
        convmma_k<3, 128, true,  false><<<g, 256, CONV_SMEM>>>(
            xhm, wm1h, wm1l, m_b1, y1h, nullptr, TMEL);
        convmma_k<3, 384, true,  false><<<g, 256, CONV_SMEM>>>(
            y1h, wm2h, wm2l, m_b2, y2h, nullptr, TMEL);
        convmma_k<1, 384, false, false><<<g, 256, CONV_SMEM>>>(
            y2h, wm3h, wm3l, m_b3, y1h, nullptr, TMEL);
    }

    // row norms: Y from hi only (matches dot operand), H from hi+lo
    rownorm2_k<<<BB * TTEXT, 128>>>(xht, xlt, hn);
    rownorm2_k<<<BB * TMEL, 128>>>(y1h, nullptr, yn);

    // fused distance + log_softmax (tensor-core, 2-term)
    {
        dim3 g(TMEL / 64, BB);
        attnmma_k<<<g, 256, ATTN_SMEM>>>(y1h, xht, xlt, yn, hn, mask, out);
    }
}

// round 12
// speedup vs baseline: 1.0260x; 1.0260x over previous
#include <cuda_runtime.h>
#include <cuda_bf16.h>
#include <math.h>
#include <stdint.h>

#define BB    32
#define TTEXT 400
#define TMEL  1600
#define ADIM  384
#define ODIM  80
#define CIPM  128   // mel input channels padded 80 -> 128

// ---------------- static scratch (no allocations allowed) ----------------
__device__ __nv_bfloat16 g_xht[(size_t)BB * TTEXT * ADIM];   // text conv2 out hi (attn H hi)
__device__ __nv_bfloat16 g_xlt[(size_t)BB * TTEXT * ADIM];   // text conv2 out lo (attn H lo)
__device__ __nv_bfloat16 g_xin[(size_t)BB * TTEXT * ADIM];   // text input hi
__device__ __nv_bfloat16 g_h1h[(size_t)BB * TTEXT * ADIM];
__device__ __nv_bfloat16 g_xhm[(size_t)BB * TMEL * CIPM];    // mel input hi (padded)
__device__ __nv_bfloat16 g_y1h[(size_t)BB * TMEL * ADIM];
__device__ __nv_bfloat16 g_y2h[(size_t)BB * TMEL * ADIM];
// weights bf16 hi/lo, layout [k][co][ci_padded]
__device__ __nv_bfloat16 g_wt1h[3 * 384 * ADIM], g_wt1l[3 * 384 * ADIM];
__device__ __nv_bfloat16 g_wt2h[1 * 384 * ADIM], g_wt2l[1 * 384 * ADIM];
__device__ __nv_bfloat16 g_wm1h[3 * 384 * CIPM], g_wm1l[3 * 384 * CIPM];
__device__ __nv_bfloat16 g_wm2h[3 * 384 * ADIM], g_wm2l[3 * 384 * ADIM];
__device__ __nv_bfloat16 g_wm3h[1 * 384 * ADIM], g_wm3l[1 * 384 * ADIM];
__device__ float g_hn[BB * TTEXT];
__device__ float g_yn[BB * TMEL];

// ---------------- PTX helpers (family-level only) ----------------
__device__ __forceinline__ unsigned int sm_u32(const void* p)
{
    return (unsigned int)__cvta_generic_to_shared(p);
}
__device__ __forceinline__ void cp16(unsigned int dst, const void* src,
                                     unsigned int bytes)
{
    asm volatile("cp.async.cg.shared.global [%0], [%1], 16, %2;"
                 :: "r"(dst), "l"(src), "r"(bytes) : "memory");
}
__device__ __forceinline__ void cp_commit()
{
    asm volatile("cp.async.commit_group;" ::: "memory");
}
template<int N>
__device__ __forceinline__ void cp_wait()
{
    asm volatile("cp.async.wait_group %0;" :: "n"(N) : "memory");
}
__device__ __forceinline__ void ldsm4(unsigned int* r, unsigned int addr)
{
    asm volatile("ldmatrix.sync.aligned.m8n8.x4.shared.b16 {%0,%1,%2,%3}, [%4];"
                 : "=r"(r[0]), "=r"(r[1]), "=r"(r[2]), "=r"(r[3]) : "r"(addr));
}
__device__ __forceinline__ void mma16816(float* c, const unsigned int* a,
                                         const unsigned int* b)
{
    asm volatile("mma.sync.aligned.m16n8k16.row.col.f32.bf16.bf16.f32 "
                 "{%0,%1,%2,%3}, {%4,%5,%6,%7}, {%8,%9}, {%0,%1,%2,%3};"
                 : "+f"(c[0]), "+f"(c[1]), "+f"(c[2]), "+f"(c[3])
                 : "r"(a[0]), "r"(a[1]), "r"(a[2]), "r"(a[3]),
                   "r"(b[0]), "r"(b[1]));
}
__device__ __forceinline__ unsigned int sw64(unsigned int bo)
{
    return bo ^ ((bo >> 3) & 0x30);
}

// ---------------- merged input split: hi only (A-side operands) ----------------
__global__ void xsplit_all_k(const float* __restrict__ hs, const float* __restrict__ ys,
                             __nv_bfloat16* __restrict__ xin, __nv_bfloat16* __restrict__ xhm)
{
    long idx = (long)blockIdx.x * 256 + threadIdx.x;
    if (blockIdx.y == 0) {
        long total = (long)BB * TTEXT * ADIM;
        if (idx >= total) return;
        xin[idx] = __float2bfloat16(hs[idx]);
    } else {
        long total = (long)BB * TMEL * CIPM;
        if (idx >= total) return;
        long r = idx >> 7;
        int  c = (int)(idx & 127);
        xhm[idx] = __float2bfloat16((c < ODIM) ? ys[r * ODIM + c] : 0.f);
    }
}

// ---------------- merged weight split: all 5 tensors (hi+lo, B-side) -------------
__device__ __forceinline__ void wsplit_one(const float* W, __nv_bfloat16* Wh,
                                           __nv_bfloat16* Wl, int CIN, int CIP,
                                           int KS, int idx)
{
    int total = KS * 384 * CIP;
    if (idx >= total) return;
    int k   = idx / (384 * CIP);
    int rem = idx - k * 384 * CIP;
    int co  = rem / CIP;
    int ci  = rem - co * CIP;
    float v = (ci < CIN) ? W[((size_t)co * CIN + ci) * KS + k] : 0.f;
    __nv_bfloat16 h = __float2bfloat16(v);
    Wh[idx] = h;
    Wl[idx] = __float2bfloat16(v - __bfloat162float(h));
}

__global__ void wsplit_all_k(const float* tw1, const float* tw2, const float* mw1,
                             const float* mw2, const float* mw3,
                             __nv_bfloat16* wt1h, __nv_bfloat16* wt1l,
                             __nv_bfloat16* wt2h, __nv_bfloat16* wt2l,
                             __nv_bfloat16* wm1h, __nv_bfloat16* wm1l,
                             __nv_bfloat16* wm2h, __nv_bfloat16* wm2l,
                             __nv_bfloat16* wm3h, __nv_bfloat16* wm3l)
{
    int idx = blockIdx.x * 256 + threadIdx.x;
    switch (blockIdx.y) {
    case 0: wsplit_one(tw1, wt1h, wt1l, ADIM, ADIM, 3, idx); break;
    case 1: wsplit_one(tw2, wt2h, wt2l, ADIM, ADIM, 1, idx); break;
    case 2: wsplit_one(mw1, wm1h, wm1l, ODIM, CIPM, 3, idx); break;
    case 3: wsplit_one(mw2, wm2h, wm2l, ADIM, ADIM, 3, idx); break;
    case 4: wsplit_one(mw3, wm3h, wm3l, ADIM, ADIM, 1, idx); break;
    }
}

// ---------------- conv1d via mma.sync, 2-term compensation (Ah*Bh + Ah*Bl) ------
// CTA tile: 64 time-rows x 128 couts, 8 warps, warp tile 32x32.
// 3-stage cp.async pipeline, single __syncthreads per K-step.
// All 12 ldsm for both kq halves issued up front, then 32 back-to-back MMAs.
// Stage = Ah(4K)+Bh(8K)+Bl(8K) = 20KB; 3 stages + bias = 62.5KB -> 2 CTAs/SM.
#define CONV_SMEM (1024 + 3 * 20480)
template<int KS, int CIP, bool RELU, bool SPLITLO>
__global__ __launch_bounds__(256, 2)
void convmma_k(const __nv_bfloat16* __restrict__ Xh,
               const __nv_bfloat16* __restrict__ Wh, const __nv_bfloat16* __restrict__ Wl,
               const float* __restrict__ bias,
               __nv_bfloat16* __restrict__ Oh, __nv_bfloat16* __restrict__ Ol, int T)
{
    constexpr int PAD = (KS - 1) / 2;
    constexpr int NC  = CIP / 32;
    constexpr int NS  = KS * NC;
    extern __shared__ char smem[];
    const unsigned int su = sm_u32(smem);

    const int tid  = threadIdx.x;
    const int lane = tid & 31;
    const int wid  = tid >> 5;
    const int wm   = wid & 1;       // 2 groups of 32 time-rows
    const int wn   = wid >> 1;      // 4 groups of 32 couts
    const int b    = blockIdx.z;
    const int t0   = blockIdx.x * 64;
    const int n0   = blockIdx.y * 128;

    float* sBias = (float*)smem;
    if (tid < 128) sBias[tid] = bias[n0 + tid];

    const int g  = lane >> 3, wi = lane & 7;
    const int arow = ((g & 1) << 3) + wi, acg = g >> 1;
    const int brow = ((g >> 1) << 3) + wi, bcg = g & 1;

    // stage layout: Ah @0 (4KB), Bh @4096 (8KB), Bl @12288 (8KB)
    auto fill = [&](int step) {
        int s  = step % 3;
        int k  = step / NC;
        int ch = step - k * NC;
        unsigned int st = su + 1024 + s * 20480;
        // A: 64 rows x 4 chunks = 256 tasks
        {
            int r = tid >> 2, c = tid & 3;
            unsigned int sw = sw64(r * 64 + c * 16);
            int t  = t0 + r + k - PAD;
            int tc = t < 0 ? 0 : (t >= T ? T - 1 : t);
            unsigned int ok = (t >= 0 && t < T) ? 16u : 0u;
            size_t src = ((size_t)b * T + tc) * CIP + ch * 32 + c * 8;
            cp16(st + sw, Xh + src, ok);
        }
        // B: 128 rows x 4 chunks x {hi,lo} = 1024 tasks
        #pragma unroll
        for (int i = tid; i < 1024; i += 256) {
            int tensor = i >> 9;
            int rem = i & 511;
            int r = rem >> 2, c = rem & 3;
            unsigned int sw = 4096 + sw64(r * 64 + c * 16) + tensor * 8192;
            size_t src = ((size_t)k * 384 + n0 + r) * CIP + ch * 32 + c * 8;
            cp16(st + sw, (tensor ? Wl : Wh) + src, 16u);
        }
        cp_commit();
    };

    float acc[2][4][4];
    #pragma unroll
    for (int i = 0; i < 2; i++)
        #pragma unroll
        for (int j = 0; j < 4; j++)
            #pragma unroll
            for (int e = 0; e < 4; e++) acc[i][j][e] = 0.f;

    fill(0);
    if (NS > 1) fill(1);
    for (int step = 0; step < NS; step++) {
        if (step == NS - 1) cp_wait<0>();
        else                cp_wait<1>();
        __syncthreads();
        if (step + 2 < NS) fill(step + 2);

        unsigned int st = su + 1024 + (step % 3) * 20480;

        // batch-load all fragments for both kq halves (12 ldsm), then 32 MMAs
        unsigned int a_h[2][2][4], b_h[2][2][4], b_l[2][2][4];
        #pragma unroll
        for (int kq = 0; kq < 2; kq++) {
            #pragma unroll
            for (int i = 0; i < 2; i++) {
                unsigned int bo = sw64((wm * 32 + i * 16 + arow) * 64
                                       + (kq * 2 + acg) * 16);
                ldsm4(a_h[kq][i], st + bo);
            }
            #pragma unroll
            for (int p = 0; p < 2; p++) {
                unsigned int bo = sw64((wn * 32 + p * 16 + brow) * 64
                                       + (kq * 2 + bcg) * 16);
                ldsm4(b_h[kq][p], st + 4096 + bo);
                ldsm4(b_l[kq][p], st + 12288 + bo);
            }
        }
        #pragma unroll
        for (int kq = 0; kq < 2; kq++)
            #pragma unroll
            for (int i = 0; i < 2; i++)
                #pragma unroll
                for (int j = 0; j < 4; j++) {
                    const unsigned int* bh2 = &b_h[kq][j >> 1][(j & 1) * 2];
                    const unsigned int* bl2 = &b_l[kq][j >> 1][(j & 1) * 2];
                    mma16816(acc[i][j], a_h[kq][i], bh2);
                    mma16816(acc[i][j], a_h[kq][i], bl2);
                }
    }

    #pragma unroll
    for (int i = 0; i < 2; i++) {
        #pragma unroll
        for (int half = 0; half < 2; half++) {
            int t = t0 + wm * 32 + i * 16 + (lane >> 2) + half * 8;
            if (t >= T) continue;
            size_t base = ((size_t)b * T + t) * 384 + n0;
            #pragma unroll
            for (int j = 0; j < 4; j++) {
                int c = wn * 32 + j * 8 + (lane & 3) * 2;
                float v0 = acc[i][j][half * 2]     + sBias[c];
                float v1 = acc[i][j][half * 2 + 1] + sBias[c + 1];
                if (RELU) { v0 = fmaxf(v0, 0.f); v1 = fmaxf(v1, 0.f); }
                __nv_bfloat16 h0 = __float2bfloat16(v0);
                __nv_bfloat16 h1 = __float2bfloat16(v1);
                __nv_bfloat162 hp; hp.x = h0; hp.y = h1;
                *(__nv_bfloat162*)&Oh[base + c] = hp;
                if (SPLITLO) {
                    __nv_bfloat162 lp;
                    lp.x = __float2bfloat16(v0 - __bfloat162float(h0));
                    lp.y = __float2bfloat16(v1 - __bfloat162float(h1));
                    *(__nv_bfloat162*)&Ol[base + c] = lp;
                }
            }
        }
    }
}

// ---------------- row squared-norms (lo optional) over 384 features -------------
__global__ void rownorm2_k(const __nv_bfloat16* __restrict__ Xh,
                           const __nv_bfloat16* __restrict__ Xl,
                           float* __restrict__ Nrm)
{
    int row = blockIdx.x;
    const __nv_bfloat16* ph = Xh + (size_t)row * 384;
    const __nv_bfloat16* pl = Xl ? Xl + (size_t)row * 384 : nullptr;
    float s = 0.f;
    for (int i = threadIdx.x; i < 384; i += 128) {
        float v = __bfloat162float(ph[i]);
        if (pl) v += __bfloat162float(pl[i]);
        s += v * v;
    }
    #pragma unroll
    for (int o = 16; o > 0; o >>= 1) s += __shfl_xor_sync(0xffffffffu, s, o);
    __shared__ float ps[4];
    if ((threadIdx.x & 31) == 0) ps[threadIdx.x >> 5] = s;
    __syncthreads();
    if (threadIdx.x == 0) Nrm[row] = ps[0] + ps[1] + ps[2] + ps[3];
}

// ---------------- fused distance mma-GEMM + sqrt + mask + log_softmax --------
// 2-term compensation (Yh*Hh + Yh*Hl).
#define ATTN_STAGE 69120
#define ATTN_SMEM  (2112 + 2 * ATTN_STAGE)
__global__ __launch_bounds__(256)
void attnmma_k(const __nv_bfloat16* __restrict__ Yh,
               const __nv_bfloat16* __restrict__ Hh, const __nv_bfloat16* __restrict__ Hl,
               const float* __restrict__ Yn, const float* __restrict__ Hn,
               const unsigned char* __restrict__ mask, float* __restrict__ Out)
{
    constexpr int NSTEP = ADIM / 32;   // 12
    extern __shared__ char smem[];
    float* sHnM = (float*)smem;
    float* sRed = (float*)(smem + 1600);
    const unsigned int su = sm_u32(smem);

    const int tid  = threadIdx.x;
    const int lane = tid & 31;
    const int wid  = tid >> 5;
    const int wm   = wid & 3;
    const int wn   = wid >> 2;
    const int b    = blockIdx.y;
    const int m0   = blockIdx.x * 64;

    for (int i = tid; i < 400; i += 256)
        sHnM[i] = mask[b * TTEXT + i] ? __int_as_float(0x7f800000) : Hn[b * TTEXT + i];

    auto fill = [&](int step) {
        int s = step & 1;
        int kc = step * 32;
        unsigned int st = su + 2112 + s * ATTN_STAGE;
        #pragma unroll 2
        for (int i = tid; i < 1600; i += 256) {
            int n = i >> 2, q = i & 3;
            unsigned int dst = st + 5120 + (n * 20 + q * 4) * 4;
            size_t src = ((size_t)b * TTEXT + n) * ADIM + kc + q * 8;
            cp16(dst,         Hh + src, 16u);
            cp16(dst + 32000, Hl + src, 16u);
        }
        {
            int i = tid;
            int r = i >> 2, q = i & 3;
            unsigned int dst = st + (r * 20 + q * 4) * 4;
            size_t src = ((size_t)b * TMEL + m0 + r) * ADIM + kc + q * 8;
            cp16(dst, Yh + src, 16u);
        }
        cp_commit();
    };

    float acc[25][4];
    #pragma unroll
    for (int j = 0; j < 25; j++)
        #pragma unroll
        for (int e = 0; e < 4; e++) acc[j][e] = 0.f;

    const int r0 = lane >> 2;
    const int lw = lane & 3;

    fill(0);
    for (int step = 0; step < NSTEP; step++) {
        int s = step & 1;
        if (step + 1 < NSTEP) { fill(step + 1); cp_wait<1>(); }
        else                  { cp_wait<0>(); }
        __syncthreads();

        const unsigned int st = su + 2112 + s * ATTN_STAGE;
        const uint32_t* Ys_h = (const uint32_t*)(smem + (st - su));
        const uint32_t* Hs_h = Ys_h + 1280;
        const uint32_t* Hs_l = Hs_h + 8000;

        #pragma unroll
        for (int kq = 0; kq < 2; kq++) {
            const int w0 = kq * 8 + lw;
            unsigned int ah[4];
            {
                int ra = (wm * 16 + r0) * 20;
                int rb = (wm * 16 + r0 + 8) * 20;
                ah[0] = Ys_h[ra + w0];     ah[1] = Ys_h[rb + w0];
                ah[2] = Ys_h[ra + w0 + 4]; ah[3] = Ys_h[rb + w0 + 4];
            }
            #pragma unroll
            for (int j = 0; j < 25; j++) {
                int n = (wn * 200 + j * 8 + r0) * 20;
                unsigned int bh[2], bl[2];
                bh[0] = Hs_h[n + w0]; bh[1] = Hs_h[n + w0 + 4];
                bl[0] = Hs_l[n + w0]; bl[1] = Hs_l[n + w0 + 4];
                mma16816(acc[j], ah, bh);
                mma16816(acc[j], ah, bl);
            }
        }
        __syncthreads();
    }

    int mrow0 = m0 + wm * 16 + r0;
    float yn0 = Yn[b * TMEL + mrow0];
    float yn1 = Yn[b * TMEL + mrow0 + 8];

    #pragma unroll
    for (int j = 0; j < 25; j++) {
        int c = wn * 200 + j * 8 + lw * 2;
        float hn0 = sHnM[c], hn1 = sHnM[c + 1];
        acc[j][0] = -sqrtf(fmaxf(yn0 + hn0 - 2.f * acc[j][0], 1e-12f));
        acc[j][1] = -sqrtf(fmaxf(yn0 + hn1 - 2.f * acc[j][1], 1e-12f));
        acc[j][2] = -sqrtf(fmaxf(yn1 + hn0 - 2.f * acc[j][2], 1e-12f));
        acc[j][3] = -sqrtf(fmaxf(yn1 + hn1 - 2.f * acc[j][3], 1e-12f));
    }

    float mx0 = -INFINITY, mx1 = -INFINITY;
    #pragma unroll
    for (int j = 0; j < 25; j++) {
        mx0 = fmaxf(mx0, fmaxf(acc[j][0], acc[j][1]));
        mx1 = fmaxf(mx1, fmaxf(acc[j][2], acc[j][3]));
    }
    #pragma unroll
    for (int o = 1; o <= 2; o <<= 1) {
        mx0 = fmaxf(mx0, __shfl_xor_sync(0xffffffffu, mx0, o));
        mx1 = fmaxf(mx1, __shfl_xor_sync(0xffffffffu, mx1, o));
    }
    if (lw == 0) {
        sRed[(wm * 16 + r0) * 2 + wn]     = mx0;
        sRed[(wm * 16 + r0 + 8) * 2 + wn] = mx1;
    }
    __syncthreads();
    mx0 = fmaxf(sRed[(wm * 16 + r0) * 2],     sRed[(wm * 16 + r0) * 2 + 1]);
    mx1 = fmaxf(sRed[(wm * 16 + r0 + 8) * 2], sRed[(wm * 16 + r0 + 8) * 2 + 1]);
    __syncthreads();

    float sm0 = 0.f, sm1 = 0.f;
    #pragma unroll
    for (int j = 0; j < 25; j++) {
        sm0 += __expf(acc[j][0] - mx0) + __expf(acc[j][1] - mx0);
        sm1 += __expf(acc[j][2] - mx1) + __expf(acc[j][3] - mx1);
    }
    #pragma unroll
    for (int o = 1; o <= 2; o <<= 1) {
        sm0 += __shfl_xor_sync(0xffffffffu, sm0, o);
        sm1 += __shfl_xor_sync(0xffffffffu, sm1, o);
    }
    if (lw == 0) {
        sRed[(wm * 16 + r0) * 2 + wn]     = sm0;
        sRed[(wm * 16 + r0 + 8) * 2 + wn] = sm1;
    }
    __syncthreads();
    sm0 = sRed[(wm * 16 + r0) * 2]     + sRed[(wm * 16 + r0) * 2 + 1];
    sm1 = sRed[(wm * 16 + r0 + 8) * 2] + sRed[(wm * 16 + r0 + 8) * 2 + 1];
    float lse0 = mx0 + __logf(sm0);
    float lse1 = mx1 + __logf(sm1);

    float* o0 = Out + ((size_t)b * TMEL + mrow0) * TTEXT;
    float* o1 = Out + ((size_t)b * TMEL + mrow0 + 8) * TTEXT;
    #pragma unroll
    for (int j = 0; j < 25; j++) {
        int c = wn * 200 + j * 8 + lw * 2;
        *(float2*)&o0[c] = make_float2(acc[j][0] - lse0, acc[j][1] - lse0);
        *(float2*)&o1[c] = make_float2(acc[j][2] - lse1, acc[j][3] - lse1);
    }
}

// ---------------- launch ----------------
extern "C" void kernel_launch(void* const* d_in, const int* in_sizes, int n_in,
                              void* d_out, int out_size)
{
    const float* hs   = (const float*)d_in[0];
    const float* ys   = (const float*)d_in[1];
    const unsigned char* mask = (const unsigned char*)d_in[2];
    const float* t_w1 = (const float*)d_in[3];
    const float* t_b1 = (const float*)d_in[4];
    const float* t_w2 = (const float*)d_in[5];
    const float* t_b2 = (const float*)d_in[6];
    const float* m_w1 = (const float*)d_in[7];
    const float* m_b1 = (const float*)d_in[8];
    const float* m_w2 = (const float*)d_in[9];
    const float* m_b2 = (const float*)d_in[10];
    const float* m_w3 = (const float*)d_in[11];
    const float* m_b3 = (const float*)d_in[12];
    float* out = (float*)d_out;

    __nv_bfloat16 *xht, *xlt, *xin, *h1h, *xhm, *y1h, *y2h;
    __nv_bfloat16 *wt1h, *wt1l, *wt2h, *wt2l, *wm1h, *wm1l, *wm2h, *wm2l, *wm3h, *wm3l;
    float *hn, *yn;
    cudaGetSymbolAddress((void**)&xht, g_xht); cudaGetSymbolAddress((void**)&xlt, g_xlt);
    cudaGetSymbolAddress((void**)&xin, g_xin); cudaGetSymbolAddress((void**)&h1h, g_h1h);
    cudaGetSymbolAddress((void**)&xhm, g_xhm);
    cudaGetSymbolAddress((void**)&y1h, g_y1h); cudaGetSymbolAddress((void**)&y2h, g_y2h);
    cudaGetSymbolAddress((void**)&wt1h, g_wt1h); cudaGetSymbolAddress((void**)&wt1l, g_wt1l);
    cudaGetSymbolAddress((void**)&wt2h, g_wt2h); cudaGetSymbolAddress((void**)&wt2l, g_wt2l);
    cudaGetSymbolAddress((void**)&wm1h, g_wm1h); cudaGetSymbolAddress((void**)&wm1l, g_wm1l);
    cudaGetSymbolAddress((void**)&wm2h, g_wm2h); cudaGetSymbolAddress((void**)&wm2l, g_wm2l);
    cudaGetSymbolAddress((void**)&wm3h, g_wm3h); cudaGetSymbolAddress((void**)&wm3l, g_wm3l);
    cudaGetSymbolAddress((void**)&hn, g_hn);   cudaGetSymbolAddress((void**)&yn, g_yn);

    cudaFuncSetAttribute(convmma_k<3, 384, true,  false>,
                         cudaFuncAttributeMaxDynamicSharedMemorySize, CONV_SMEM);
    cudaFuncSetAttribute(convmma_k<1, 384, false, true >,
                         cudaFuncAttributeMaxDynamicSharedMemorySize, CONV_SMEM);
    cudaFuncSetAttribute(convmma_k<1, 384, false, false>,
                         cudaFuncAttributeMaxDynamicSharedMemorySize, CONV_SMEM);
    cudaFuncSetAttribute(convmma_k<3, 128, true,  false>,
                         cudaFuncAttributeMaxDynamicSharedMemorySize, CONV_SMEM);
    cudaFuncSetAttribute(attnmma_k,
                         cudaFuncAttributeMaxDynamicSharedMemorySize, ATTN_SMEM);

    // #0: merged input split (hi only)
    {
        long mel = (long)BB * TMEL * CIPM;
        dim3 g((unsigned)((mel + 255) / 256), 2);
        xsplit_all_k<<<g, 256>>>(hs, ys, xin, xhm);
    }
    // #1: merged weight split
    {
        dim3 g((3 * 384 * ADIM + 255) / 256, 5);
        wsplit_all_k<<<g, 256>>>(t_w1, t_w2, m_w1, m_w2, m_w3,
                                 wt1h, wt1l, wt2h, wt2l, wm1h, wm1l,
                                 wm2h, wm2l, wm3h, wm3l);
    }

    // #2-#3: text prenet (conv2 output feeds attn B side -> hi+lo)
    {
        dim3 g((TTEXT + 63) / 64, 3, BB);
        convmma_k<3, 384, true,  false><<<g, 256, CONV_SMEM>>>(
            xin, wt1h, wt1l, t_b1, h1h, nullptr, TTEXT);
        convmma_k<1, 384, false, true ><<<g, 256, CONV_SMEM>>>(
            h1h, wt2h, wt2l, t_b2, xht, xlt, TTEXT);
    }
    // #4-#6: mel prenet (#5 = mel conv2, the ncu-profiled launch)
    {
        dim3 g((TMEL + 63) / 64, 3, BB);
        convmma_k<3, 128, true,  false><<<g, 256, CONV_SMEM>>>(
            xhm, wm1h, wm1l, m_b1, y1h, nullptr, TMEL);
        convmma_k<3, 384, true,  false><<<g, 256, CONV_SMEM>>>(
            y1h, wm2h, wm2l, m_b2, y2h, nullptr, TMEL);
        convmma_k<1, 384, false, false><<<g, 256, CONV_SMEM>>>(
            y2h, wm3h, wm3l, m_b3, y1h, nullptr, TMEL);
    }

    // row norms: Y from hi only (matches dot operand), H from hi+lo
    rownorm2_k<<<BB * TTEXT, 128>>>(xht, xlt, hn);
    rownorm2_k<<<BB * TMEL, 128>>>(y1h, nullptr, yn);

    // fused distance + log_softmax (tensor-core, 2-term)
    {
        dim3 g(TMEL / 64, BB);
        attnmma_k<<<g, 256, ATTN_SMEM>>>(y1h, xht, xlt, yn, hn, mask, out);
    }
}

// round 13
// speedup vs baseline: 1.0568x; 1.0300x over previous
#include <cuda_runtime.h>
#include <cuda_bf16.h>
#include <math.h>
#include <stdint.h>

#define BB    32
#define TTEXT 400
#define TMEL  1600
#define ADIM  384
#define ODIM  80
#define CIPM  128   // mel input channels padded 80 -> 128

// ---------------- static scratch (no allocations allowed) ----------------
__device__ __nv_bfloat16 g_xht[(size_t)BB * TTEXT * ADIM];   // text conv2 out hi (attn H hi)
__device__ __nv_bfloat16 g_xlt[(size_t)BB * TTEXT * ADIM];   // text conv2 out lo (attn H lo)
__device__ __nv_bfloat16 g_xin[(size_t)BB * TTEXT * ADIM];   // text input hi
__device__ __nv_bfloat16 g_h1h[(size_t)BB * TTEXT * ADIM];
__device__ __nv_bfloat16 g_xhm[(size_t)BB * TMEL * CIPM];    // mel input hi (padded)
__device__ __nv_bfloat16 g_y1h[(size_t)BB * TMEL * ADIM];
__device__ __nv_bfloat16 g_y2h[(size_t)BB * TMEL * ADIM];
// weights bf16 hi/lo, layout [k][co][ci_padded]
__device__ __nv_bfloat16 g_wt1h[3 * 384 * ADIM], g_wt1l[3 * 384 * ADIM];
__device__ __nv_bfloat16 g_wt2h[1 * 384 * ADIM], g_wt2l[1 * 384 * ADIM];
__device__ __nv_bfloat16 g_wm1h[3 * 384 * CIPM], g_wm1l[3 * 384 * CIPM];
__device__ __nv_bfloat16 g_wm2h[3 * 384 * ADIM], g_wm2l[3 * 384 * ADIM];
__device__ __nv_bfloat16 g_wm3h[1 * 384 * ADIM], g_wm3l[1 * 384 * ADIM];
__device__ float g_hn[BB * TTEXT];
__device__ float g_yn[BB * TMEL];

// ---------------- PTX helpers (family-level only) ----------------
__device__ __forceinline__ unsigned int sm_u32(const void* p)
{
    return (unsigned int)__cvta_generic_to_shared(p);
}
__device__ __forceinline__ void cp16(unsigned int dst, const void* src,
                                     unsigned int bytes)
{
    asm volatile("cp.async.cg.shared.global [%0], [%1], 16, %2;"
                 :: "r"(dst), "l"(src), "r"(bytes) : "memory");
}
__device__ __forceinline__ void cp_commit()
{
    asm volatile("cp.async.commit_group;" ::: "memory");
}
template<int N>
__device__ __forceinline__ void cp_wait()
{
    asm volatile("cp.async.wait_group %0;" :: "n"(N) : "memory");
}
__device__ __forceinline__ void ldsm4(unsigned int* r, unsigned int addr)
{
    asm volatile("ldmatrix.sync.aligned.m8n8.x4.shared.b16 {%0,%1,%2,%3}, [%4];"
                 : "=r"(r[0]), "=r"(r[1]), "=r"(r[2]), "=r"(r[3]) : "r"(addr));
}
__device__ __forceinline__ void mma16816(float* c, const unsigned int* a,
                                         const unsigned int* b)
{
    asm volatile("mma.sync.aligned.m16n8k16.row.col.f32.bf16.bf16.f32 "
                 "{%0,%1,%2,%3}, {%4,%5,%6,%7}, {%8,%9}, {%0,%1,%2,%3};"
                 : "+f"(c[0]), "+f"(c[1]), "+f"(c[2]), "+f"(c[3])
                 : "r"(a[0]), "r"(a[1]), "r"(a[2]), "r"(a[3]),
                   "r"(b[0]), "r"(b[1]));
}
__device__ __forceinline__ unsigned int sw64(unsigned int bo)
{
    return bo ^ ((bo >> 3) & 0x30);
}

// ---------------- merged input split: hi only (A-side operands) ----------------
__global__ void xsplit_all_k(const float* __restrict__ hs, const float* __restrict__ ys,
                             __nv_bfloat16* __restrict__ xin, __nv_bfloat16* __restrict__ xhm)
{
    long idx = (long)blockIdx.x * 256 + threadIdx.x;
    if (blockIdx.y == 0) {
        long total = (long)BB * TTEXT * ADIM;
        if (idx >= total) return;
        xin[idx] = __float2bfloat16(hs[idx]);
    } else {
        long total = (long)BB * TMEL * CIPM;
        if (idx >= total) return;
        long r = idx >> 7;
        int  c = (int)(idx & 127);
        xhm[idx] = __float2bfloat16((c < ODIM) ? ys[r * ODIM + c] : 0.f);
    }
}

// ---------------- merged weight split: all 5 tensors (hi+lo, B-side) -------------
__device__ __forceinline__ void wsplit_one(const float* W, __nv_bfloat16* Wh,
                                           __nv_bfloat16* Wl, int CIN, int CIP,
                                           int KS, int idx)
{
    int total = KS * 384 * CIP;
    if (idx >= total) return;
    int k   = idx / (384 * CIP);
    int rem = idx - k * 384 * CIP;
    int co  = rem / CIP;
    int ci  = rem - co * CIP;
    float v = (ci < CIN) ? W[((size_t)co * CIN + ci) * KS + k] : 0.f;
    __nv_bfloat16 h = __float2bfloat16(v);
    Wh[idx] = h;
    Wl[idx] = __float2bfloat16(v - __bfloat162float(h));
}

__global__ void wsplit_all_k(const float* tw1, const float* tw2, const float* mw1,
                             const float* mw2, const float* mw3,
                             __nv_bfloat16* wt1h, __nv_bfloat16* wt1l,
                             __nv_bfloat16* wt2h, __nv_bfloat16* wt2l,
                             __nv_bfloat16* wm1h, __nv_bfloat16* wm1l,
                             __nv_bfloat16* wm2h, __nv_bfloat16* wm2l,
                             __nv_bfloat16* wm3h, __nv_bfloat16* wm3l)
{
    int idx = blockIdx.x * 256 + threadIdx.x;
    switch (blockIdx.y) {
    case 0: wsplit_one(tw1, wt1h, wt1l, ADIM, ADIM, 3, idx); break;
    case 1: wsplit_one(tw2, wt2h, wt2l, ADIM, ADIM, 1, idx); break;
    case 2: wsplit_one(mw1, wm1h, wm1l, ODIM, CIPM, 3, idx); break;
    case 3: wsplit_one(mw2, wm2h, wm2l, ADIM, ADIM, 3, idx); break;
    case 4: wsplit_one(mw3, wm3h, wm3l, ADIM, ADIM, 1, idx); break;
    }
}

// ---------------- conv1d via mma.sync, 2-term compensation, TAP-FUSED ------------
// CTA tile: 64 time-rows x 128 couts, 8 warps, warp tile 32x32.
// One pipeline step per 32-channel chunk; all KS taps processed from one stage:
//  A with halo (64+KS-1 rows, loaded once), B = KS taps x {hi,lo}.
// KS==3: 2 stages of 52.5KB (safe order: wait -> sync -> fill(next)).
// KS==1: 3 stages of 20KB (R9 pattern).
template<int KS> struct ConvCfg;
template<> struct ConvCfg<3> { static const int ARB = 4608, NSTG = 2; };
template<> struct ConvCfg<1> { static const int ARB = 4096, NSTG = 3; };
#define CONV_STAGE(KS)  (ConvCfg<KS>::ARB + KS * 16384)
#define CONV_SMEM(KS)   (1024 + ConvCfg<KS>::NSTG * CONV_STAGE(KS))

template<int KS, int CIP, bool RELU, bool SPLITLO>
__global__ __launch_bounds__(256, 2)
void convmma_k(const __nv_bfloat16* __restrict__ Xh,
               const __nv_bfloat16* __restrict__ Wh, const __nv_bfloat16* __restrict__ Wl,
               const float* __restrict__ bias,
               __nv_bfloat16* __restrict__ Oh, __nv_bfloat16* __restrict__ Ol, int T)
{
    constexpr int PAD   = (KS - 1) / 2;
    constexpr int NS    = CIP / 32;           // steps = channel chunks
    constexpr int AR    = 64 + KS - 1;        // A rows incl. halo
    constexpr int ARB   = ConvCfg<KS>::ARB;
    constexpr int NSTG  = ConvCfg<KS>::NSTG;
    constexpr int STAGE = ARB + KS * 16384;
    extern __shared__ char smem[];
    const unsigned int su = sm_u32(smem);

    const int tid  = threadIdx.x;
    const int lane = tid & 31;
    const int wid  = tid >> 5;
    const int wm   = wid & 1;       // 2 groups of 32 time-rows
    const int wn   = wid >> 1;      // 4 groups of 32 couts
    const int b    = blockIdx.z;
    const int t0   = blockIdx.x * 64;
    const int n0   = blockIdx.y * 128;

    float* sBias = (float*)smem;
    if (tid < 128) sBias[tid] = bias[n0 + tid];

    const int g  = lane >> 3, wi = lane & 7;
    const int arow = ((g & 1) << 3) + wi, acg = g >> 1;
    const int brow = ((g >> 1) << 3) + wi, bcg = g & 1;

    // stage: A @0 (ARB), then per tap: Bh @ARB+tap*16384, Bl @+8192
    auto fill = [&](int step) {
        int ch = step;
        unsigned int st = su + 1024 + (step % NSTG) * STAGE;
        #pragma unroll
        for (int i = tid; i < AR * 4; i += 256) {
            int r = i >> 2, c = i & 3;
            unsigned int sw = sw64(r * 64 + c * 16);
            int t  = t0 + r - PAD;
            int tc = t < 0 ? 0 : (t >= T ? T - 1 : t);
            unsigned int ok = (t >= 0 && t < T) ? 16u : 0u;
            size_t src = ((size_t)b * T + tc) * CIP + ch * 32 + c * 8;
            cp16(st + sw, Xh + src, ok);
        }
        #pragma unroll
        for (int i = tid; i < KS * 1024; i += 256) {
            int tap  = i >> 10;
            int rem  = i & 1023;
            int tensor = rem >> 9;
            int rem2 = rem & 511;
            int r = rem2 >> 2, c = rem2 & 3;
            unsigned int dst = st + ARB + tap * 16384 + tensor * 8192
                             + sw64(r * 64 + c * 16);
            size_t src = ((size_t)tap * 384 + n0 + r) * CIP + ch * 32 + c * 8;
            cp16(dst, (tensor ? Wl : Wh) + src, 16u);
        }
        cp_commit();
    };

    float acc[2][4][4];
    #pragma unroll
    for (int i = 0; i < 2; i++)
        #pragma unroll
        for (int j = 0; j < 4; j++)
            #pragma unroll
            for (int e = 0; e < 4; e++) acc[i][j][e] = 0.f;

    auto compute = [&](int step) {
        unsigned int st = su + 1024 + (step % NSTG) * STAGE;
        #pragma unroll
        for (int k = 0; k < KS; k++) {
            unsigned int bb = st + ARB + k * 16384;
            #pragma unroll
            for (int kq = 0; kq < 2; kq++) {
                unsigned int a_h[2][4], b_h[2][4], b_l[2][4];
                #pragma unroll
                for (int i = 0; i < 2; i++) {
                    unsigned int bo = sw64((wm * 32 + i * 16 + arow + k) * 64
                                           + (kq * 2 + acg) * 16);
                    ldsm4(a_h[i], st + bo);
                }
                #pragma unroll
                for (int p = 0; p < 2; p++) {
                    unsigned int bo = sw64((wn * 32 + p * 16 + brow) * 64
                                           + (kq * 2 + bcg) * 16);
                    ldsm4(b_h[p], bb + bo);
                    ldsm4(b_l[p], bb + 8192 + bo);
                }
                #pragma unroll
                for (int i = 0; i < 2; i++)
                    #pragma unroll
                    for (int j = 0; j < 4; j++) {
                        const unsigned int* bh2 = &b_h[j >> 1][(j & 1) * 2];
                        const unsigned int* bl2 = &b_l[j >> 1][(j & 1) * 2];
                        mma16816(acc[i][j], a_h[i], bh2);
                        mma16816(acc[i][j], a_h[i], bl2);
                    }
            }
        }
    };

    if (NSTG == 3) {
        fill(0);
        if (NS > 1) fill(1);
        for (int step = 0; step < NS; step++) {
            if (step == NS - 1) cp_wait<0>();
            else                cp_wait<1>();
            __syncthreads();
            if (step + 2 < NS) fill(step + 2);
            compute(step);
        }
    } else {
        fill(0);
        for (int step = 0; step < NS; step++) {
            cp_wait<0>();
            __syncthreads();
            if (step + 1 < NS) fill(step + 1);
            compute(step);
        }
    }

    #pragma unroll
    for (int i = 0; i < 2; i++) {
        #pragma unroll
        for (int half = 0; half < 2; half++) {
            int t = t0 + wm * 32 + i * 16 + (lane >> 2) + half * 8;
            if (t >= T) continue;
            size_t base = ((size_t)b * T + t) * 384 + n0;
            #pragma unroll
            for (int j = 0; j < 4; j++) {
                int c = wn * 32 + j * 8 + (lane & 3) * 2;
                float v0 = acc[i][j][half * 2]     + sBias[c];
                float v1 = acc[i][j][half * 2 + 1] + sBias[c + 1];
                if (RELU) { v0 = fmaxf(v0, 0.f); v1 = fmaxf(v1, 0.f); }
                __nv_bfloat16 h0 = __float2bfloat16(v0);
                __nv_bfloat16 h1 = __float2bfloat16(v1);
                __nv_bfloat162 hp; hp.x = h0; hp.y = h1;
                *(__nv_bfloat162*)&Oh[base + c] = hp;
                if (SPLITLO) {
                    __nv_bfloat162 lp;
                    lp.x = __float2bfloat16(v0 - __bfloat162float(h0));
                    lp.y = __float2bfloat16(v1 - __bfloat162float(h1));
                    *(__nv_bfloat162*)&Ol[base + c] = lp;
                }
            }
        }
    }
}

// ---------------- row squared-norms (lo optional) over 384 features -------------
__global__ void rownorm2_k(const __nv_bfloat16* __restrict__ Xh,
                           const __nv_bfloat16* __restrict__ Xl,
                           float* __restrict__ Nrm)
{
    int row = blockIdx.x;
    const __nv_bfloat16* ph = Xh + (size_t)row * 384;
    const __nv_bfloat16* pl = Xl ? Xl + (size_t)row * 384 : nullptr;
    float s = 0.f;
    for (int i = threadIdx.x; i < 384; i += 128) {
        float v = __bfloat162float(ph[i]);
        if (pl) v += __bfloat162float(pl[i]);
        s += v * v;
    }
    #pragma unroll
    for (int o = 16; o > 0; o >>= 1) s += __shfl_xor_sync(0xffffffffu, s, o);
    __shared__ float ps[4];
    if ((threadIdx.x & 31) == 0) ps[threadIdx.x >> 5] = s;
    __syncthreads();
    if (threadIdx.x == 0) Nrm[row] = ps[0] + ps[1] + ps[2] + ps[3];
}

// ---------------- fused distance mma-GEMM + sqrt + mask + log_softmax --------
// 2-term compensation (Yh*Hh + Yh*Hl).
#define ATTN_STAGE 69120
#define ATTN_SMEM  (2112 + 2 * ATTN_STAGE)
__global__ __launch_bounds__(256)
void attnmma_k(const __nv_bfloat16* __restrict__ Yh,
               const __nv_bfloat16* __restrict__ Hh, const __nv_bfloat16* __restrict__ Hl,
               const float* __restrict__ Yn, const float* __restrict__ Hn,
               const unsigned char* __restrict__ mask, float* __restrict__ Out)
{
    constexpr int NSTEP = ADIM / 32;   // 12
    extern __shared__ char smem[];
    float* sHnM = (float*)smem;
    float* sRed = (float*)(smem + 1600);
    const unsigned int su = sm_u32(smem);

    const int tid  = threadIdx.x;
    const int lane = tid & 31;
    const int wid  = tid >> 5;
    const int wm   = wid & 3;
    const int wn   = wid >> 2;
    const int b    = blockIdx.y;
    const int m0   = blockIdx.x * 64;

    for (int i = tid; i < 400; i += 256)
        sHnM[i] = mask[b * TTEXT + i] ? __int_as_float(0x7f800000) : Hn[b * TTEXT + i];

    auto fill = [&](int step) {
        int s = step & 1;
        int kc = step * 32;
        unsigned int st = su + 2112 + s * ATTN_STAGE;
        #pragma unroll 2
        for (int i = tid; i < 1600; i += 256) {
            int n = i >> 2, q = i & 3;
            unsigned int dst = st + 5120 + (n * 20 + q * 4) * 4;
            size_t src = ((size_t)b * TTEXT + n) * ADIM + kc + q * 8;
            cp16(dst,         Hh + src, 16u);
            cp16(dst + 32000, Hl + src, 16u);
        }
        {
            int i = tid;
            int r = i >> 2, q = i & 3;
            unsigned int dst = st + (r * 20 + q * 4) * 4;
            size_t src = ((size_t)b * TMEL + m0 + r) * ADIM + kc + q * 8;
            cp16(dst, Yh + src, 16u);
        }
        cp_commit();
    };

    float acc[25][4];
    #pragma unroll
    for (int j = 0; j < 25; j++)
        #pragma unroll
        for (int e = 0; e < 4; e++) acc[j][e] = 0.f;

    const int r0 = lane >> 2;
    const int lw = lane & 3;

    fill(0);
    for (int step = 0; step < NSTEP; step++) {
        int s = step & 1;
        if (step + 1 < NSTEP) { fill(step + 1); cp_wait<1>(); }
        else                  { cp_wait<0>(); }
        __syncthreads();

        const unsigned int st = su + 2112 + s * ATTN_STAGE;
        const uint32_t* Ys_h = (const uint32_t*)(smem + (st - su));
        const uint32_t* Hs_h = Ys_h + 1280;
        const uint32_t* Hs_l = Hs_h + 8000;

        #pragma unroll
        for (int kq = 0; kq < 2; kq++) {
            const int w0 = kq * 8 + lw;
            unsigned int ah[4];
            {
                int ra = (wm * 16 + r0) * 20;
                int rb = (wm * 16 + r0 + 8) * 20;
                ah[0] = Ys_h[ra + w0];     ah[1] = Ys_h[rb + w0];
                ah[2] = Ys_h[ra + w0 + 4]; ah[3] = Ys_h[rb + w0 + 4];
            }
            #pragma unroll
            for (int j = 0; j < 25; j++) {
                int n = (wn * 200 + j * 8 + r0) * 20;
                unsigned int bh[2], bl[2];
                bh[0] = Hs_h[n + w0]; bh[1] = Hs_h[n + w0 + 4];
                bl[0] = Hs_l[n + w0]; bl[1] = Hs_l[n + w0 + 4];
                mma16816(acc[j], ah, bh);
                mma16816(acc[j], ah, bl);
            }
        }
        __syncthreads();
    }

    int mrow0 = m0 + wm * 16 + r0;
    float yn0 = Yn[b * TMEL + mrow0];
    float yn1 = Yn[b * TMEL + mrow0 + 8];

    #pragma unroll
    for (int j = 0; j < 25; j++) {
        int c = wn * 200 + j * 8 + lw * 2;
        float hn0 = sHnM[c], hn1 = sHnM[c + 1];
        acc[j][0] = -sqrtf(fmaxf(yn0 + hn0 - 2.f * acc[j][0], 1e-12f));
        acc[j][1] = -sqrtf(fmaxf(yn0 + hn1 - 2.f * acc[j][1], 1e-12f));
        acc[j][2] = -sqrtf(fmaxf(yn1 + hn0 - 2.f * acc[j][2], 1e-12f));
        acc[j][3] = -sqrtf(fmaxf(yn1 + hn1 - 2.f * acc[j][3], 1e-12f));
    }

    float mx0 = -INFINITY, mx1 = -INFINITY;
    #pragma unroll
    for (int j = 0; j < 25; j++) {
        mx0 = fmaxf(mx0, fmaxf(acc[j][0], acc[j][1]));
        mx1 = fmaxf(mx1, fmaxf(acc[j][2], acc[j][3]));
    }
    #pragma unroll
    for (int o = 1; o <= 2; o <<= 1) {
        mx0 = fmaxf(mx0, __shfl_xor_sync(0xffffffffu, mx0, o));
        mx1 = fmaxf(mx1, __shfl_xor_sync(0xffffffffu, mx1, o));
    }
    if (lw == 0) {
        sRed[(wm * 16 + r0) * 2 + wn]     = mx0;
        sRed[(wm * 16 + r0 + 8) * 2 + wn] = mx1;
    }
    __syncthreads();
    mx0 = fmaxf(sRed[(wm * 16 + r0) * 2],     sRed[(wm * 16 + r0) * 2 + 1]);
    mx1 = fmaxf(sRed[(wm * 16 + r0 + 8) * 2], sRed[(wm * 16 + r0 + 8) * 2 + 1]);
    __syncthreads();

    float sm0 = 0.f, sm1 = 0.f;
    #pragma unroll
    for (int j = 0; j < 25; j++) {
        sm0 += __expf(acc[j][0] - mx0) + __expf(acc[j][1] - mx0);
        sm1 += __expf(acc[j][2] - mx1) + __expf(acc[j][3] - mx1);
    }
    #pragma unroll
    for (int o = 1; o <= 2; o <<= 1) {
        sm0 += __shfl_xor_sync(0xffffffffu, sm0, o);
        sm1 += __shfl_xor_sync(0xffffffffu, sm1, o);
    }
    if (lw == 0) {
        sRed[(wm * 16 + r0) * 2 + wn]     = sm0;
        sRed[(wm * 16 + r0 + 8) * 2 + wn] = sm1;
    }
    __syncthreads();
    sm0 = sRed[(wm * 16 + r0) * 2]     + sRed[(wm * 16 + r0) * 2 + 1];
    sm1 = sRed[(wm * 16 + r0 + 8) * 2] + sRed[(wm * 16 + r0 + 8) * 2 + 1];
    float lse0 = mx0 + __logf(sm0);
    float lse1 = mx1 + __logf(sm1);

    float* o0 = Out + ((size_t)b * TMEL + mrow0) * TTEXT;
    float* o1 = Out + ((size_t)b * TMEL + mrow0 + 8) * TTEXT;
    #pragma unroll
    for (int j = 0; j < 25; j++) {
        int c = wn * 200 + j * 8 + lw * 2;
        *(float2*)&o0[c] = make_float2(acc[j][0] - lse0, acc[j][1] - lse0);
        *(float2*)&o1[c] = make_float2(acc[j][2] - lse1, acc[j][3] - lse1);
    }
}

// ---------------- launch ----------------
extern "C" void kernel_launch(void* const* d_in, const int* in_sizes, int n_in,
                              void* d_out, int out_size)
{
    const float* hs   = (const float*)d_in[0];
    const float* ys   = (const float*)d_in[1];
    const unsigned char* mask = (const unsigned char*)d_in[2];
    const float* t_w1 = (const float*)d_in[3];
    const float* t_b1 = (const float*)d_in[4];
    const float* t_w2 = (const float*)d_in[5];
    const float* t_b2 = (const float*)d_in[6];
    const float* m_w1 = (const float*)d_in[7];
    const float* m_b1 = (const float*)d_in[8];
    const float* m_w2 = (const float*)d_in[9];
    const float* m_b2 = (const float*)d_in[10];
    const float* m_w3 = (const float*)d_in[11];
    const float* m_b3 = (const float*)d_in[12];
    float* out = (float*)d_out;

    __nv_bfloat16 *xht, *xlt, *xin, *h1h, *xhm, *y1h, *y2h;
    __nv_bfloat16 *wt1h, *wt1l, *wt2h, *wt2l, *wm1h, *wm1l, *wm2h, *wm2l, *wm3h, *wm3l;
    float *hn, *yn;
    cudaGetSymbolAddress((void**)&xht, g_xht); cudaGetSymbolAddress((void**)&xlt, g_xlt);
    cudaGetSymbolAddress((void**)&xin, g_xin); cudaGetSymbolAddress((void**)&h1h, g_h1h);
    cudaGetSymbolAddress((void**)&xhm, g_xhm);
    cudaGetSymbolAddress((void**)&y1h, g_y1h); cudaGetSymbolAddress((void**)&y2h, g_y2h);
    cudaGetSymbolAddress((void**)&wt1h, g_wt1h); cudaGetSymbolAddress((void**)&wt1l, g_wt1l);
    cudaGetSymbolAddress((void**)&wt2h, g_wt2h); cudaGetSymbolAddress((void**)&wt2l, g_wt2l);
    cudaGetSymbolAddress((void**)&wm1h, g_wm1h); cudaGetSymbolAddress((void**)&wm1l, g_wm1l);
    cudaGetSymbolAddress((void**)&wm2h, g_wm2h); cudaGetSymbolAddress((void**)&wm2l, g_wm2l);
    cudaGetSymbolAddress((void**)&wm3h, g_wm3h); cudaGetSymbolAddress((void**)&wm3l, g_wm3l);
    cudaGetSymbolAddress((void**)&hn, g_hn);   cudaGetSymbolAddress((void**)&yn, g_yn);

    cudaFuncSetAttribute(convmma_k<3, 384, true,  false>,
                         cudaFuncAttributeMaxDynamicSharedMemorySize, CONV_SMEM(3));
    cudaFuncSetAttribute(convmma_k<1, 384, false, true >,
                         cudaFuncAttributeMaxDynamicSharedMemorySize, CONV_SMEM(1));
    cudaFuncSetAttribute(convmma_k<1, 384, false, false>,
                         cudaFuncAttributeMaxDynamicSharedMemorySize, CONV_SMEM(1));
    cudaFuncSetAttribute(convmma_k<3, 128, true,  false>,
                         cudaFuncAttributeMaxDynamicSharedMemorySize, CONV_SMEM(3));
    cudaFuncSetAttribute(attnmma_k,
                         cudaFuncAttributeMaxDynamicSharedMemorySize, ATTN_SMEM);

    // #0: merged input split (hi only)
    {
        long mel = (long)BB * TMEL * CIPM;
        dim3 g((unsigned)((mel + 255) / 256), 2);
        xsplit_all_k<<<g, 256>>>(hs, ys, xin, xhm);
    }
    // #1: merged weight split
    {
        dim3 g((3 * 384 * ADIM + 255) / 256, 5);
        wsplit_all_k<<<g, 256>>>(t_w1, t_w2, m_w1, m_w2, m_w3,
                                 wt1h, wt1l, wt2h, wt2l, wm1h, wm1l,
                                 wm2h, wm2l, wm3h, wm3l);
    }

    // #2-#3: text prenet (conv2 output feeds attn B side -> hi+lo)
    {
        dim3 g((TTEXT + 63) / 64, 3, BB);
        convmma_k<3, 384, true,  false><<<g, 256, CONV_SMEM(3)>>>(
            xin, wt1h, wt1l, t_b1, h1h, nullptr, TTEXT);
        convmma_k<1, 384, false, true ><<<g, 256, CONV_SMEM(1)>>>(
            h1h, wt2h, wt2l, t_b2, xht, xlt, TTEXT);
    }
    // #4-#6: mel prenet (#5 = m-conv2, the ncu-profiled launch)
    {
        dim3 g((TMEL + 63) / 64, 3, BB);
        convmma_k<3, 128, true,  false><<<g, 256, CONV_SMEM(3)>>>(
            xhm, wm1h, wm1l, m_b1, y1h, nullptr, TMEL);
        convmma_k<3, 384, true,  false><<<g, 256, CONV_SMEM(3)>>>(
            y1h, wm2h, wm2l, m_b2, y2h, nullptr, TMEL);
        convmma_k<1, 384, false, false><<<g, 256, CONV_SMEM(1)>>>(
            y2h, wm3h, wm3l, m_b3, y1h, nullptr, TMEL);
    }

    // row norms: Y from hi only (matches dot operand), H from hi+lo
    rownorm2_k<<<BB * TTEXT, 128>>>(xht, xlt, hn);
    rownorm2_k<<<BB * TMEL, 128>>>(y1h, nullptr, yn);

    // fused distance + log_softmax (tensor-core, 2-term)
    {
        dim3 g(TMEL / 64, BB);
        attnmma_k<<<g, 256, ATTN_SMEM>>>(y1h, xht, xlt, yn, hn, mask, out);
    }
}

// round 14
// speedup vs baseline: 1.6745x; 1.5845x over previous
#include <cuda_runtime.h>
#include <cuda_fp16.h>
#include <math.h>
#include <stdint.h>

#define BB    32
#define TTEXT 400
#define TMEL  1600
#define ADIM  384
#define ODIM  80
#define CIPM  128   // mel input channels padded 80 -> 128

// ---------------- static scratch (no allocations allowed) ----------------
__device__ __half g_xht[(size_t)BB * TTEXT * ADIM];   // text conv2 out (attn H)
__device__ __half g_xin[(size_t)BB * TTEXT * ADIM];   // text input
__device__ __half g_h1h[(size_t)BB * TTEXT * ADIM];
__device__ __half g_xhm[(size_t)BB * TMEL * CIPM];    // mel input (padded)
__device__ __half g_y1h[(size_t)BB * TMEL * ADIM];
__device__ __half g_y2h[(size_t)BB * TMEL * ADIM];
// weights fp16, layout [k][co][ci_padded]
__device__ __half g_wt1[3 * 384 * ADIM];
__device__ __half g_wt2[1 * 384 * ADIM];
__device__ __half g_wm1[3 * 384 * CIPM];
__device__ __half g_wm2[3 * 384 * ADIM];
__device__ __half g_wm3[1 * 384 * ADIM];
__device__ float g_hn[BB * TTEXT];
__device__ float g_yn[BB * TMEL];

// ---------------- PTX helpers (family-level only) ----------------
__device__ __forceinline__ unsigned int sm_u32(const void* p)
{
    return (unsigned int)__cvta_generic_to_shared(p);
}
__device__ __forceinline__ void cp16(unsigned int dst, const void* src,
                                     unsigned int bytes)
{
    asm volatile("cp.async.cg.shared.global [%0], [%1], 16, %2;"
                 :: "r"(dst), "l"(src), "r"(bytes) : "memory");
}
__device__ __forceinline__ void cp_commit()
{
    asm volatile("cp.async.commit_group;" ::: "memory");
}
template<int N>
__device__ __forceinline__ void cp_wait()
{
    asm volatile("cp.async.wait_group %0;" :: "n"(N) : "memory");
}
__device__ __forceinline__ void ldsm4(unsigned int* r, unsigned int addr)
{
    asm volatile("ldmatrix.sync.aligned.m8n8.x4.shared.b16 {%0,%1,%2,%3}, [%4];"
                 : "=r"(r[0]), "=r"(r[1]), "=r"(r[2]), "=r"(r[3]) : "r"(addr));
}
__device__ __forceinline__ void mma16816(float* c, const unsigned int* a,
                                         const unsigned int* b)
{
    asm volatile("mma.sync.aligned.m16n8k16.row.col.f32.f16.f16.f32 "
                 "{%0,%1,%2,%3}, {%4,%5,%6,%7}, {%8,%9}, {%0,%1,%2,%3};"
                 : "+f"(c[0]), "+f"(c[1]), "+f"(c[2]), "+f"(c[3])
                 : "r"(a[0]), "r"(a[1]), "r"(a[2]), "r"(a[3]),
                   "r"(b[0]), "r"(b[1]));
}
__device__ __forceinline__ unsigned int sw64(unsigned int bo)
{
    return bo ^ ((bo >> 3) & 0x30);
}

// ---------------- merged input split: fp16 ----------------
__global__ void xsplit_all_k(const float* __restrict__ hs, const float* __restrict__ ys,
                             __half* __restrict__ xin, __half* __restrict__ xhm)
{
    long idx = (long)blockIdx.x * 256 + threadIdx.x;
    if (blockIdx.y == 0) {
        long total = (long)BB * TTEXT * ADIM;
        if (idx >= total) return;
        xin[idx] = __float2half(hs[idx]);
    } else {
        long total = (long)BB * TMEL * CIPM;
        if (idx >= total) return;
        long r = idx >> 7;
        int  c = (int)(idx & 127);
        xhm[idx] = __float2half((c < ODIM) ? ys[r * ODIM + c] : 0.f);
    }
}

// ---------------- merged weight split: all 5 tensors, single fp16 ---------------
__device__ __forceinline__ void wsplit_one(const float* W, __half* Wh,
                                           int CIN, int CIP, int KS, int idx)
{
    int total = KS * 384 * CIP;
    if (idx >= total) return;
    int k   = idx / (384 * CIP);
    int rem = idx - k * 384 * CIP;
    int co  = rem / CIP;
    int ci  = rem - co * CIP;
    float v = (ci < CIN) ? W[((size_t)co * CIN + ci) * KS + k] : 0.f;
    Wh[idx] = __float2half(v);
}

__global__ void wsplit_all_k(const float* tw1, const float* tw2, const float* mw1,
                             const float* mw2, const float* mw3,
                             __half* wt1, __half* wt2, __half* wm1,
                             __half* wm2, __half* wm3)
{
    int idx = blockIdx.x * 256 + threadIdx.x;
    switch (blockIdx.y) {
    case 0: wsplit_one(tw1, wt1, ADIM, ADIM, 3, idx); break;
    case 1: wsplit_one(tw2, wt2, ADIM, ADIM, 1, idx); break;
    case 2: wsplit_one(mw1, wm1, ODIM, CIPM, 3, idx); break;
    case 3: wsplit_one(mw2, wm2, ADIM, ADIM, 3, idx); break;
    case 4: wsplit_one(mw3, wm3, ADIM, ADIM, 1, idx); break;
    }
}

// ---------------- conv1d via single-term fp16 mma.sync, TAP-FUSED ---------------
// CTA tile: 64 time-rows x 128 couts, 8 warps, warp tile 32x32.
// One pipeline step per 32-channel chunk; A loaded once with halo; KS B taps.
// 3-stage cp.async pipeline, single __syncthreads per step.
template<int KS> struct ConvCfg;
template<> struct ConvCfg<3> { static const int ARB = 4608; };
template<> struct ConvCfg<1> { static const int ARB = 4096; };
#define CONV_STAGE(KS)  (ConvCfg<KS>::ARB + KS * 8192)
#define CONV_SMEM(KS)   (1024 + 3 * CONV_STAGE(KS))

template<int KS, int CIP, bool RELU>
__global__ __launch_bounds__(256, 2)
void convmma_k(const __half* __restrict__ Xh, const __half* __restrict__ Wh,
               const float* __restrict__ bias, __half* __restrict__ Oh, int T)
{
    constexpr int PAD   = (KS - 1) / 2;
    constexpr int NS    = CIP / 32;           // steps = channel chunks
    constexpr int AR    = 64 + KS - 1;        // A rows incl. halo
    constexpr int ARB   = ConvCfg<KS>::ARB;
    constexpr int STAGE = ARB + KS * 8192;
    extern __shared__ char smem[];
    const unsigned int su = sm_u32(smem);

    const int tid  = threadIdx.x;
    const int lane = tid & 31;
    const int wid  = tid >> 5;
    const int wm   = wid & 1;       // 2 groups of 32 time-rows
    const int wn   = wid >> 1;      // 4 groups of 32 couts
    const int b    = blockIdx.z;
    const int t0   = blockIdx.x * 64;
    const int n0   = blockIdx.y * 128;

    float* sBias = (float*)smem;
    if (tid < 128) sBias[tid] = bias[n0 + tid];

    const int g  = lane >> 3, wi = lane & 7;
    const int arow = ((g & 1) << 3) + wi, acg = g >> 1;
    const int brow = ((g >> 1) << 3) + wi, bcg = g & 1;

    // stage: A @0 (ARB), then per tap: B @ARB + tap*8192
    auto fill = [&](int step) {
        int ch = step;
        unsigned int st = su + 1024 + (step % 3) * STAGE;
        #pragma unroll
        for (int i = tid; i < AR * 4; i += 256) {
            int r = i >> 2, c = i & 3;
            unsigned int sw = sw64(r * 64 + c * 16);
            int t  = t0 + r - PAD;
            int tc = t < 0 ? 0 : (t >= T ? T - 1 : t);
            unsigned int ok = (t >= 0 && t < T) ? 16u : 0u;
            size_t src = ((size_t)b * T + tc) * CIP + ch * 32 + c * 8;
            cp16(st + sw, Xh + src, ok);
        }
        #pragma unroll
        for (int i = tid; i < KS * 512; i += 256) {
            int tap = i >> 9;
            int rem = i & 511;
            int r = rem >> 2, c = rem & 3;
            unsigned int dst = st + ARB + tap * 8192 + sw64(r * 64 + c * 16);
            size_t src = ((size_t)tap * 384 + n0 + r) * CIP + ch * 32 + c * 8;
            cp16(dst, Wh + src, 16u);
        }
        cp_commit();
    };

    float acc[2][4][4];
    #pragma unroll
    for (int i = 0; i < 2; i++)
        #pragma unroll
        for (int j = 0; j < 4; j++)
            #pragma unroll
            for (int e = 0; e < 4; e++) acc[i][j][e] = 0.f;

    fill(0);
    if (NS > 1) fill(1);
    for (int step = 0; step < NS; step++) {
        if (step == NS - 1) cp_wait<0>();
        else                cp_wait<1>();
        __syncthreads();
        if (step + 2 < NS) fill(step + 2);

        unsigned int st = su + 1024 + (step % 3) * STAGE;
        #pragma unroll
        for (int k = 0; k < KS; k++) {
            unsigned int bb = st + ARB + k * 8192;
            #pragma unroll
            for (int kq = 0; kq < 2; kq++) {
                unsigned int a_h[2][4], b_h[2][4];
                #pragma unroll
                for (int i = 0; i < 2; i++) {
                    unsigned int bo = sw64((wm * 32 + i * 16 + arow + k) * 64
                                           + (kq * 2 + acg) * 16);
                    ldsm4(a_h[i], st + bo);
                }
                #pragma unroll
                for (int p = 0; p < 2; p++) {
                    unsigned int bo = sw64((wn * 32 + p * 16 + brow) * 64
                                           + (kq * 2 + bcg) * 16);
                    ldsm4(b_h[p], bb + bo);
                }
                #pragma unroll
                for (int i = 0; i < 2; i++)
                    #pragma unroll
                    for (int j = 0; j < 4; j++)
                        mma16816(acc[i][j], a_h[i], &b_h[j >> 1][(j & 1) * 2]);
            }
        }
    }

    #pragma unroll
    for (int i = 0; i < 2; i++) {
        #pragma unroll
        for (int half = 0; half < 2; half++) {
            int t = t0 + wm * 32 + i * 16 + (lane >> 2) + half * 8;
            if (t >= T) continue;
            size_t base = ((size_t)b * T + t) * 384 + n0;
            #pragma unroll
            for (int j = 0; j < 4; j++) {
                int c = wn * 32 + j * 8 + (lane & 3) * 2;
                float v0 = acc[i][j][half * 2]     + sBias[c];
                float v1 = acc[i][j][half * 2 + 1] + sBias[c + 1];
                if (RELU) { v0 = fmaxf(v0, 0.f); v1 = fmaxf(v1, 0.f); }
                __half2 hp;
                hp.x = __float2half(v0); hp.y = __float2half(v1);
                *(__half2*)&Oh[base + c] = hp;
            }
        }
    }
}

// ---------------- row squared-norms over 384 features ----------------
__global__ void rownorm2_k(const __half* __restrict__ Xh, float* __restrict__ Nrm)
{
    int row = blockIdx.x;
    const __half* ph = Xh + (size_t)row * 384;
    float s = 0.f;
    for (int i = threadIdx.x; i < 384; i += 128) {
        float v = __half2float(ph[i]);
        s += v * v;
    }
    #pragma unroll
    for (int o = 16; o > 0; o >>= 1) s += __shfl_xor_sync(0xffffffffu, s, o);
    __shared__ float ps[4];
    if ((threadIdx.x & 31) == 0) ps[threadIdx.x >> 5] = s;
    __syncthreads();
    if (threadIdx.x == 0) Nrm[row] = ps[0] + ps[1] + ps[2] + ps[3];
}

// ---------------- fused distance mma-GEMM + sqrt + mask + log_softmax --------
// single-term fp16: dot(Yq, Hq) exact in fp32 accum.
#define ATTN_STAGE 37120
#define ATTN_SMEM  (2112 + 2 * ATTN_STAGE)
__global__ __launch_bounds__(256)
void attnmma_k(const __half* __restrict__ Yh, const __half* __restrict__ Hh,
               const float* __restrict__ Yn, const float* __restrict__ Hn,
               const unsigned char* __restrict__ mask, float* __restrict__ Out)
{
    constexpr int NSTEP = ADIM / 32;   // 12
    extern __shared__ char smem[];
    float* sHnM = (float*)smem;
    float* sRed = (float*)(smem + 1600);
    const unsigned int su = sm_u32(smem);

    const int tid  = threadIdx.x;
    const int lane = tid & 31;
    const int wid  = tid >> 5;
    const int wm   = wid & 3;
    const int wn   = wid >> 2;
    const int b    = blockIdx.y;
    const int m0   = blockIdx.x * 64;

    for (int i = tid; i < 400; i += 256)
        sHnM[i] = mask[b * TTEXT + i] ? __int_as_float(0x7f800000) : Hn[b * TTEXT + i];

    // stage (pitch 20 words/row): Y[64][20] @0, H[400][20] @5120B
    auto fill = [&](int step) {
        int s = step & 1;
        int kc = step * 32;
        unsigned int st = su + 2112 + s * ATTN_STAGE;
        #pragma unroll 2
        for (int i = tid; i < 1600; i += 256) {
            int n = i >> 2, q = i & 3;
            unsigned int dst = st + 5120 + (n * 20 + q * 4) * 4;
            size_t src = ((size_t)b * TTEXT + n) * ADIM + kc + q * 8;
            cp16(dst, Hh + src, 16u);
        }
        {
            int i = tid;
            int r = i >> 2, q = i & 3;
            unsigned int dst = st + (r * 20 + q * 4) * 4;
            size_t src = ((size_t)b * TMEL + m0 + r) * ADIM + kc + q * 8;
            cp16(dst, Yh + src, 16u);
        }
        cp_commit();
    };

    float acc[25][4];
    #pragma unroll
    for (int j = 0; j < 25; j++)
        #pragma unroll
        for (int e = 0; e < 4; e++) acc[j][e] = 0.f;

    const int r0 = lane >> 2;
    const int lw = lane & 3;

    fill(0);
    for (int step = 0; step < NSTEP; step++) {
        int s = step & 1;
        if (step + 1 < NSTEP) { fill(step + 1); cp_wait<1>(); }
        else                  { cp_wait<0>(); }
        __syncthreads();

        const unsigned int st = su + 2112 + s * ATTN_STAGE;
        const uint32_t* Ys_h = (const uint32_t*)(smem + (st - su));
        const uint32_t* Hs_h = Ys_h + 1280;

        #pragma unroll
        for (int kq = 0; kq < 2; kq++) {
            const int w0 = kq * 8 + lw;
            unsigned int ah[4];
            {
                int ra = (wm * 16 + r0) * 20;
                int rb = (wm * 16 + r0 + 8) * 20;
                ah[0] = Ys_h[ra + w0];     ah[1] = Ys_h[rb + w0];
                ah[2] = Ys_h[ra + w0 + 4]; ah[3] = Ys_h[rb + w0 + 4];
            }
            #pragma unroll
            for (int j = 0; j < 25; j++) {
                int n = (wn * 200 + j * 8 + r0) * 20;
                unsigned int bh[2];
                bh[0] = Hs_h[n + w0]; bh[1] = Hs_h[n + w0 + 4];
                mma16816(acc[j], ah, bh);
            }
        }
        __syncthreads();
    }

    int mrow0 = m0 + wm * 16 + r0;
    float yn0 = Yn[b * TMEL + mrow0];
    float yn1 = Yn[b * TMEL + mrow0 + 8];

    #pragma unroll
    for (int j = 0; j < 25; j++) {
        int c = wn * 200 + j * 8 + lw * 2;
        float hn0 = sHnM[c], hn1 = sHnM[c + 1];
        acc[j][0] = -sqrtf(fmaxf(yn0 + hn0 - 2.f * acc[j][0], 1e-12f));
        acc[j][1] = -sqrtf(fmaxf(yn0 + hn1 - 2.f * acc[j][1], 1e-12f));
        acc[j][2] = -sqrtf(fmaxf(yn1 + hn0 - 2.f * acc[j][2], 1e-12f));
        acc[j][3] = -sqrtf(fmaxf(yn1 + hn1 - 2.f * acc[j][3], 1e-12f));
    }

    float mx0 = -INFINITY, mx1 = -INFINITY;
    #pragma unroll
    for (int j = 0; j < 25; j++) {
        mx0 = fmaxf(mx0, fmaxf(acc[j][0], acc[j][1]));
        mx1 = fmaxf(mx1, fmaxf(acc[j][2], acc[j][3]));
    }
    #pragma unroll
    for (int o = 1; o <= 2; o <<= 1) {
        mx0 = fmaxf(mx0, __shfl_xor_sync(0xffffffffu, mx0, o));
        mx1 = fmaxf(mx1, __shfl_xor_sync(0xffffffffu, mx1, o));
    }
    if (lw == 0) {
        sRed[(wm * 16 + r0) * 2 + wn]     = mx0;
        sRed[(wm * 16 + r0 + 8) * 2 + wn] = mx1;
    }
    __syncthreads();
    mx0 = fmaxf(sRed[(wm * 16 + r0) * 2],     sRed[(wm * 16 + r0) * 2 + 1]);
    mx1 = fmaxf(sRed[(wm * 16 + r0 + 8) * 2], sRed[(wm * 16 + r0 + 8) * 2 + 1]);
    __syncthreads();

    float sm0 = 0.f, sm1 = 0.f;
    #pragma unroll
    for (int j = 0; j < 25; j++) {
        sm0 += __expf(acc[j][0] - mx0) + __expf(acc[j][1] - mx0);
        sm1 += __expf(acc[j][2] - mx1) + __expf(acc[j][3] - mx1);
    }
    #pragma unroll
    for (int o = 1; o <= 2; o <<= 1) {
        sm0 += __shfl_xor_sync(0xffffffffu, sm0, o);
        sm1 += __shfl_xor_sync(0xffffffffu, sm1, o);
    }
    if (lw == 0) {
        sRed[(wm * 16 + r0) * 2 + wn]     = sm0;
        sRed[(wm * 16 + r0 + 8) * 2 + wn] = sm1;
    }
    __syncthreads();
    sm0 = sRed[(wm * 16 + r0) * 2]     + sRed[(wm * 16 + r0) * 2 + 1];
    sm1 = sRed[(wm * 16 + r0 + 8) * 2] + sRed[(wm * 16 + r0 + 8) * 2 + 1];
    float lse0 = mx0 + __logf(sm0);
    float lse1 = mx1 + __logf(sm1);

    float* o0 = Out + ((size_t)b * TMEL + mrow0) * TTEXT;
    float* o1 = Out + ((size_t)b * TMEL + mrow0 + 8) * TTEXT;
    #pragma unroll
    for (int j = 0; j < 25; j++) {
        int c = wn * 200 + j * 8 + lw * 2;
        *(float2*)&o0[c] = make_float2(acc[j][0] - lse0, acc[j][1] - lse0);
        *(float2*)&o1[c] = make_float2(acc[j][2] - lse1, acc[j][3] - lse1);
    }
}

// ---------------- launch ----------------
extern "C" void kernel_launch(void* const* d_in, const int* in_sizes, int n_in,
                              void* d_out, int out_size)
{
    const float* hs   = (const float*)d_in[0];
    const float* ys   = (const float*)d_in[1];
    const unsigned char* mask = (const unsigned char*)d_in[2];
    const float* t_w1 = (const float*)d_in[3];
    const float* t_b1 = (const float*)d_in[4];
    const float* t_w2 = (const float*)d_in[5];
    const float* t_b2 = (const float*)d_in[6];
    const float* m_w1 = (const float*)d_in[7];
    const float* m_b1 = (const float*)d_in[8];
    const float* m_w2 = (const float*)d_in[9];
    const float* m_b2 = (const float*)d_in[10];
    const float* m_w3 = (const float*)d_in[11];
    const float* m_b3 = (const float*)d_in[12];
    float* out = (float*)d_out;

    __half *xht, *xin, *h1h, *xhm, *y1h, *y2h;
    __half *wt1, *wt2, *wm1, *wm2, *wm3;
    float *hn, *yn;
    cudaGetSymbolAddress((void**)&xht, g_xht);
    cudaGetSymbolAddress((void**)&xin, g_xin); cudaGetSymbolAddress((void**)&h1h, g_h1h);
    cudaGetSymbolAddress((void**)&xhm, g_xhm);
    cudaGetSymbolAddress((void**)&y1h, g_y1h); cudaGetSymbolAddress((void**)&y2h, g_y2h);
    cudaGetSymbolAddress((void**)&wt1, g_wt1); cudaGetSymbolAddress((void**)&wt2, g_wt2);
    cudaGetSymbolAddress((void**)&wm1, g_wm1); cudaGetSymbolAddress((void**)&wm2, g_wm2);
    cudaGetSymbolAddress((void**)&wm3, g_wm3);
    cudaGetSymbolAddress((void**)&hn, g_hn);   cudaGetSymbolAddress((void**)&yn, g_yn);

    cudaFuncSetAttribute(convmma_k<3, 384, true >,
                         cudaFuncAttributeMaxDynamicSharedMemorySize, CONV_SMEM(3));
    cudaFuncSetAttribute(convmma_k<1, 384, false>,
                         cudaFuncAttributeMaxDynamicSharedMemorySize, CONV_SMEM(1));
    cudaFuncSetAttribute(convmma_k<3, 128, true >,
                         cudaFuncAttributeMaxDynamicSharedMemorySize, CONV_SMEM(3));
    cudaFuncSetAttribute(attnmma_k,
                         cudaFuncAttributeMaxDynamicSharedMemorySize, ATTN_SMEM);

    // #0: merged input split (fp16)
    {
        long mel = (long)BB * TMEL * CIPM;
        dim3 g((unsigned)((mel + 255) / 256), 2);
        xsplit_all_k<<<g, 256>>>(hs, ys, xin, xhm);
    }
    // #1: merged weight split (fp16)
    {
        dim3 g((3 * 384 * ADIM + 255) / 256, 5);
        wsplit_all_k<<<g, 256>>>(t_w1, t_w2, m_w1, m_w2, m_w3,
                                 wt1, wt2, wm1, wm2, wm3);
    }

    // #2-#3: text prenet
    {
        dim3 g((TTEXT + 63) / 64, 3, BB);
        convmma_k<3, 384, true ><<<g, 256, CONV_SMEM(3)>>>(
            xin, wt1, t_b1, h1h, TTEXT);
        convmma_k<1, 384, false><<<g, 256, CONV_SMEM(1)>>>(
            h1h, wt2, t_b2, xht, TTEXT);
    }
    // #4-#6: mel prenet (#5 = m-conv2, the ncu-profiled launch)
    {
        dim3 g((TMEL + 63) / 64, 3, BB);
        convmma_k<3, 128, true ><<<g, 256, CONV_SMEM(3)>>>(
            xhm, wm1, m_b1, y1h, TMEL);
        convmma_k<3, 384, true ><<<g, 256, CONV_SMEM(3)>>>(
            y1h, wm2, m_b2, y2h, TMEL);
        convmma_k<1, 384, false><<<g, 256, CONV_SMEM(1)>>>(
            y2h, wm3, m_b3, y1h, TMEL);
    }

    // row norms from the exact fp16 operands the dot uses
    rownorm2_k<<<BB * TTEXT, 128>>>(xht, hn);
    rownorm2_k<<<BB * TMEL, 128>>>(y1h, yn);

    // fused distance + log_softmax (single-term fp16 tensor-core)
    {
        dim3 g(TMEL / 64, BB);
        attnmma_k<<<g, 256, ATTN_SMEM>>>(y1h, xht, yn, hn, mask, out);
    }
}

// round 15
// speedup vs baseline: 1.7337x; 1.0353x over previous
#include <cuda_runtime.h>
#include <cuda_fp16.h>
#include <math.h>
#include <stdint.h>

#define BB    32
#define TTEXT 400
#define TMEL  1600
#define ADIM  384
#define ODIM  80
#define CIPM  128   // mel input channels padded 80 -> 128

// ---------------- static scratch (no allocations allowed) ----------------
__device__ __half g_xht[(size_t)BB * TTEXT * ADIM];   // text conv2 out (attn H)
__device__ __half g_xin[(size_t)BB * TTEXT * ADIM];   // text input
__device__ __half g_h1h[(size_t)BB * TTEXT * ADIM];
__device__ __half g_xhm[(size_t)BB * TMEL * CIPM];    // mel input (padded)
__device__ __half g_y1h[(size_t)BB * TMEL * ADIM];
__device__ __half g_y2h[(size_t)BB * TMEL * ADIM];
// weights fp16, layout [k][co][ci_padded]
__device__ __half g_wt1[3 * 384 * ADIM];
__device__ __half g_wt2[1 * 384 * ADIM];
__device__ __half g_wm1[3 * 384 * CIPM];
__device__ __half g_wm2[3 * 384 * ADIM];
__device__ __half g_wm3[1 * 384 * ADIM];
__device__ float g_hn[BB * TTEXT];
__device__ float g_yn[BB * TMEL];

// ---------------- PTX helpers (family-level only) ----------------
__device__ __forceinline__ unsigned int sm_u32(const void* p)
{
    return (unsigned int)__cvta_generic_to_shared(p);
}
__device__ __forceinline__ void cp16(unsigned int dst, const void* src,
                                     unsigned int bytes)
{
    asm volatile("cp.async.cg.shared.global [%0], [%1], 16, %2;"
                 :: "r"(dst), "l"(src), "r"(bytes) : "memory");
}
__device__ __forceinline__ void cp_commit()
{
    asm volatile("cp.async.commit_group;" ::: "memory");
}
template<int N>
__device__ __forceinline__ void cp_wait()
{
    asm volatile("cp.async.wait_group %0;" :: "n"(N) : "memory");
}
__device__ __forceinline__ void ldsm4(unsigned int* r, unsigned int addr)
{
    asm volatile("ldmatrix.sync.aligned.m8n8.x4.shared.b16 {%0,%1,%2,%3}, [%4];"
                 : "=r"(r[0]), "=r"(r[1]), "=r"(r[2]), "=r"(r[3]) : "r"(addr));
}
__device__ __forceinline__ void mma16816(float* c, const unsigned int* a,
                                         const unsigned int* b)
{
    asm volatile("mma.sync.aligned.m16n8k16.row.col.f32.f16.f16.f32 "
                 "{%0,%1,%2,%3}, {%4,%5,%6,%7}, {%8,%9}, {%0,%1,%2,%3};"
                 : "+f"(c[0]), "+f"(c[1]), "+f"(c[2]), "+f"(c[3])
                 : "r"(a[0]), "r"(a[1]), "r"(a[2]), "r"(a[3]),
                   "r"(b[0]), "r"(b[1]));
}
__device__ __forceinline__ unsigned int sw64(unsigned int bo)
{
    return bo ^ ((bo >> 3) & 0x30);
}

// ---------------- merged input split: fp16 ----------------
__global__ void xsplit_all_k(const float* __restrict__ hs, const float* __restrict__ ys,
                             __half* __restrict__ xin, __half* __restrict__ xhm)
{
    long idx = (long)blockIdx.x * 256 + threadIdx.x;
    if (blockIdx.y == 0) {
        long total = (long)BB * TTEXT * ADIM;
        if (idx >= total) return;
        xin[idx] = __float2half(hs[idx]);
    } else {
        long total = (long)BB * TMEL * CIPM;
        if (idx >= total) return;
        long r = idx >> 7;
        int  c = (int)(idx & 127);
        xhm[idx] = __float2half((c < ODIM) ? ys[r * ODIM + c] : 0.f);
    }
}

// ---------------- merged weight split: all 5 tensors, single fp16 ---------------
__device__ __forceinline__ void wsplit_one(const float* W, __half* Wh,
                                           int CIN, int CIP, int KS, int idx)
{
    int total = KS * 384 * CIP;
    if (idx >= total) return;
    int k   = idx / (384 * CIP);
    int rem = idx - k * 384 * CIP;
    int co  = rem / CIP;
    int ci  = rem - co * CIP;
    float v = (ci < CIN) ? W[((size_t)co * CIN + ci) * KS + k] : 0.f;
    Wh[idx] = __float2half(v);
}

__global__ void wsplit_all_k(const float* tw1, const float* tw2, const float* mw1,
                             const float* mw2, const float* mw3,
                             __half* wt1, __half* wt2, __half* wm1,
                             __half* wm2, __half* wm3)
{
    int idx = blockIdx.x * 256 + threadIdx.x;
    switch (blockIdx.y) {
    case 0: wsplit_one(tw1, wt1, ADIM, ADIM, 3, idx); break;
    case 1: wsplit_one(tw2, wt2, ADIM, ADIM, 1, idx); break;
    case 2: wsplit_one(mw1, wm1, ODIM, CIPM, 3, idx); break;
    case 3: wsplit_one(mw2, wm2, ADIM, ADIM, 3, idx); break;
    case 4: wsplit_one(mw3, wm3, ADIM, ADIM, 1, idx); break;
    }
}

// ---------------- conv1d via single-term fp16 mma.sync, TAP-FUSED ---------------
// CTA tile: 128 time-rows x 128 couts, 8 warps, warp tile 64x32 (wm 2 x wn 4).
// One pipeline step per 32-channel chunk; A loaded once with halo; KS B taps.
// 3-stage cp.async pipeline, single __syncthreads per step.
template<int KS> struct ConvCfg;
template<> struct ConvCfg<3> { static const int ARB = 8448; };  // 130 rows + pad
template<> struct ConvCfg<1> { static const int ARB = 8192; };  // 128 rows
#define CONV_STAGE(KS)  (ConvCfg<KS>::ARB + KS * 8192)
#define CONV_SMEM(KS)   (1024 + 3 * CONV_STAGE(KS))

template<int KS, int CIP, bool RELU>
__global__ __launch_bounds__(256, 2)
void convmma_k(const __half* __restrict__ Xh, const __half* __restrict__ Wh,
               const float* __restrict__ bias, __half* __restrict__ Oh, int T)
{
    constexpr int PAD   = (KS - 1) / 2;
    constexpr int NS    = CIP / 32;           // steps = channel chunks
    constexpr int AR    = 128 + KS - 1;       // A rows incl. halo
    constexpr int ARB   = ConvCfg<KS>::ARB;
    constexpr int STAGE = ARB + KS * 8192;
    extern __shared__ char smem[];
    const unsigned int su = sm_u32(smem);

    const int tid  = threadIdx.x;
    const int lane = tid & 31;
    const int wid  = tid >> 5;
    const int wm   = wid & 1;       // 2 groups of 64 time-rows
    const int wn   = wid >> 1;      // 4 groups of 32 couts
    const int b    = blockIdx.z;
    const int t0   = blockIdx.x * 128;
    const int n0   = blockIdx.y * 128;

    float* sBias = (float*)smem;
    if (tid < 128) sBias[tid] = bias[n0 + tid];

    const int g  = lane >> 3, wi = lane & 7;
    const int arow = ((g & 1) << 3) + wi, acg = g >> 1;
    const int brow = ((g >> 1) << 3) + wi, bcg = g & 1;

    // stage: A @0 (ARB), then per tap: B @ARB + tap*8192
    auto fill = [&](int step) {
        int ch = step;
        unsigned int st = su + 1024 + (step % 3) * STAGE;
        #pragma unroll
        for (int i = tid; i < AR * 4; i += 256) {
            int r = i >> 2, c = i & 3;
            unsigned int sw = sw64(r * 64 + c * 16);
            int t  = t0 + r - PAD;
            int tc = t < 0 ? 0 : (t >= T ? T - 1 : t);
            unsigned int ok = (t >= 0 && t < T) ? 16u : 0u;
            size_t src = ((size_t)b * T + tc) * CIP + ch * 32 + c * 8;
            cp16(st + sw, Xh + src, ok);
        }
        #pragma unroll
        for (int i = tid; i < KS * 512; i += 256) {
            int tap = i >> 9;
            int rem = i & 511;
            int r = rem >> 2, c = rem & 3;
            unsigned int dst = st + ARB + tap * 8192 + sw64(r * 64 + c * 16);
            size_t src = ((size_t)tap * 384 + n0 + r) * CIP + ch * 32 + c * 8;
            cp16(dst, Wh + src, 16u);
        }
        cp_commit();
    };

    float acc[4][4][4];
    #pragma unroll
    for (int i = 0; i < 4; i++)
        #pragma unroll
        for (int j = 0; j < 4; j++)
            #pragma unroll
            for (int e = 0; e < 4; e++) acc[i][j][e] = 0.f;

    fill(0);
    if (NS > 1) fill(1);
    for (int step = 0; step < NS; step++) {
        if (step == NS - 1) cp_wait<0>();
        else                cp_wait<1>();
        __syncthreads();
        if (step + 2 < NS) fill(step + 2);

        unsigned int st = su + 1024 + (step % 3) * STAGE;
        #pragma unroll
        for (int k = 0; k < KS; k++) {
            unsigned int bb = st + ARB + k * 8192;
            #pragma unroll
            for (int kq = 0; kq < 2; kq++) {
                unsigned int a_h[4][4], b_h[2][4];
                #pragma unroll
                for (int i = 0; i < 4; i++) {
                    unsigned int bo = sw64((wm * 64 + i * 16 + arow + k) * 64
                                           + (kq * 2 + acg) * 16);
                    ldsm4(a_h[i], st + bo);
                }
                #pragma unroll
                for (int p = 0; p < 2; p++) {
                    unsigned int bo = sw64((wn * 32 + p * 16 + brow) * 64
                                           + (kq * 2 + bcg) * 16);
                    ldsm4(b_h[p], bb + bo);
                }
                #pragma unroll
                for (int i = 0; i < 4; i++)
                    #pragma unroll
                    for (int j = 0; j < 4; j++)
                        mma16816(acc[i][j], a_h[i], &b_h[j >> 1][(j & 1) * 2]);
            }
        }
    }

    #pragma unroll
    for (int i = 0; i < 4; i++) {
        #pragma unroll
        for (int half = 0; half < 2; half++) {
            int t = t0 + wm * 64 + i * 16 + (lane >> 2) + half * 8;
            if (t >= T) continue;
            size_t base = ((size_t)b * T + t) * 384 + n0;
            #pragma unroll
            for (int j = 0; j < 4; j++) {
                int c = wn * 32 + j * 8 + (lane & 3) * 2;
                float v0 = acc[i][j][half * 2]     + sBias[c];
                float v1 = acc[i][j][half * 2 + 1] + sBias[c + 1];
                if (RELU) { v0 = fmaxf(v0, 0.f); v1 = fmaxf(v1, 0.f); }
                __half2 hp;
                hp.x = __float2half(v0); hp.y = __float2half(v1);
                *(__half2*)&Oh[base + c] = hp;
            }
        }
    }
}

// ---------------- row squared-norms over 384 features ----------------
__global__ void rownorm2_k(const __half* __restrict__ Xh, float* __restrict__ Nrm)
{
    int row = blockIdx.x;
    const __half* ph = Xh + (size_t)row * 384;
    float s = 0.f;
    for (int i = threadIdx.x; i < 384; i += 128) {
        float v = __half2float(ph[i]);
        s += v * v;
    }
    #pragma unroll
    for (int o = 16; o > 0; o >>= 1) s += __shfl_xor_sync(0xffffffffu, s, o);
    __shared__ float ps[4];
    if ((threadIdx.x & 31) == 0) ps[threadIdx.x >> 5] = s;
    __syncthreads();
    if (threadIdx.x == 0) Nrm[row] = ps[0] + ps[1] + ps[2] + ps[3];
}

// ---------------- fused distance mma-GEMM + sqrt + mask + log_softmax --------
// single-term fp16: dot(Yq, Hq) in fp32 accum.
#define ATTN_STAGE 37120
#define ATTN_SMEM  (2112 + 2 * ATTN_STAGE)
__global__ __launch_bounds__(256)
void attnmma_k(const __half* __restrict__ Yh, const __half* __restrict__ Hh,
               const float* __restrict__ Yn, const float* __restrict__ Hn,
               const unsigned char* __restrict__ mask, float* __restrict__ Out)
{
    constexpr int NSTEP = ADIM / 32;   // 12
    extern __shared__ char smem[];
    float* sHnM = (float*)smem;
    float* sRed = (float*)(smem + 1600);
    const unsigned int su = sm_u32(smem);

    const int tid  = threadIdx.x;
    const int lane = tid & 31;
    const int wid  = tid >> 5;
    const int wm   = wid & 3;
    const int wn   = wid >> 2;
    const int b    = blockIdx.y;
    const int m0   = blockIdx.x * 64;

    for (int i = tid; i < 400; i += 256)
        sHnM[i] = mask[b * TTEXT + i] ? __int_as_float(0x7f800000) : Hn[b * TTEXT + i];

    // stage (pitch 20 words/row): Y[64][20] @0, H[400][20] @5120B
    auto fill = [&](int step) {
        int s = step & 1;
        int kc = step * 32;
        unsigned int st = su + 2112 + s * ATTN_STAGE;
        #pragma unroll 2
        for (int i = tid; i < 1600; i += 256) {
            int n = i >> 2, q = i & 3;
            unsigned int dst = st + 5120 + (n * 20 + q * 4) * 4;
            size_t src = ((size_t)b * TTEXT + n) * ADIM + kc + q * 8;
            cp16(dst, Hh + src, 16u);
        }
        {
            int i = tid;
            int r = i >> 2, q = i & 3;
            unsigned int dst = st + (r * 20 + q * 4) * 4;
            size_t src = ((size_t)b * TMEL + m0 + r) * ADIM + kc + q * 8;
            cp16(dst, Yh + src, 16u);
        }
        cp_commit();
    };

    float acc[25][4];
    #pragma unroll
    for (int j = 0; j < 25; j++)
        #pragma unroll
        for (int e = 0; e < 4; e++) acc[j][e] = 0.f;

    const int r0 = lane >> 2;
    const int lw = lane & 3;

    fill(0);
    for (int step = 0; step < NSTEP; step++) {
        int s = step & 1;
        if (step + 1 < NSTEP) { fill(step + 1); cp_wait<1>(); }
        else                  { cp_wait<0>(); }
        __syncthreads();

        const unsigned int st = su + 2112 + s * ATTN_STAGE;
        const uint32_t* Ys_h = (const uint32_t*)(smem + (st - su));
        const uint32_t* Hs_h = Ys_h + 1280;

        #pragma unroll
        for (int kq = 0; kq < 2; kq++) {
            const int w0 = kq * 8 + lw;
            unsigned int ah[4];
            {
                int ra = (wm * 16 + r0) * 20;
                int rb = (wm * 16 + r0 + 8) * 20;
                ah[0] = Ys_h[ra + w0];     ah[1] = Ys_h[rb + w0];
                ah[2] = Ys_h[ra + w0 + 4]; ah[3] = Ys_h[rb + w0 + 4];
            }
            #pragma unroll
            for (int j = 0; j < 25; j++) {
                int n = (wn * 200 + j * 8 + r0) * 20;
                unsigned int bh[2];
                bh[0] = Hs_h[n + w0]; bh[1] = Hs_h[n + w0 + 4];
                mma16816(acc[j], ah, bh);
            }
        }
        __syncthreads();
    }

    int mrow0 = m0 + wm * 16 + r0;
    float yn0 = Yn[b * TMEL + mrow0];
    float yn1 = Yn[b * TMEL + mrow0 + 8];

    #pragma unroll
    for (int j = 0; j < 25; j++) {
        int c = wn * 200 + j * 8 + lw * 2;
        float hn0 = sHnM[c], hn1 = sHnM[c + 1];
        acc[j][0] = -sqrtf(fmaxf(yn0 + hn0 - 2.f * acc[j][0], 1e-12f));
        acc[j][1] = -sqrtf(fmaxf(yn0 + hn1 - 2.f * acc[j][1], 1e-12f));
        acc[j][2] = -sqrtf(fmaxf(yn1 + hn0 - 2.f * acc[j][2], 1e-12f));
        acc[j][3] = -sqrtf(fmaxf(yn1 + hn1 - 2.f * acc[j][3], 1e-12f));
    }

    float mx0 = -INFINITY, mx1 = -INFINITY;
    #pragma unroll
    for (int j = 0; j < 25; j++) {
        mx0 = fmaxf(mx0, fmaxf(acc[j][0], acc[j][1]));
        mx1 = fmaxf(mx1, fmaxf(acc[j][2], acc[j][3]));
    }
    #pragma unroll
    for (int o = 1; o <= 2; o <<= 1) {
        mx0 = fmaxf(mx0, __shfl_xor_sync(0xffffffffu, mx0, o));
        mx1 = fmaxf(mx1, __shfl_xor_sync(0xffffffffu, mx1, o));
    }
    if (lw == 0) {
        sRed[(wm * 16 + r0) * 2 + wn]     = mx0;
        sRed[(wm * 16 + r0 + 8) * 2 + wn] = mx1;
    }
    __syncthreads();
    mx0 = fmaxf(sRed[(wm * 16 + r0) * 2],     sRed[(wm * 16 + r0) * 2 + 1]);
    mx1 = fmaxf(sRed[(wm * 16 + r0 + 8) * 2], sRed[(wm * 16 + r0 + 8) * 2 + 1]);
    __syncthreads();

    float sm0 = 0.f, sm1 = 0.f;
    #pragma unroll
    for (int j = 0; j < 25; j++) {
        sm0 += __expf(acc[j][0] - mx0) + __expf(acc[j][1] - mx0);
        sm1 += __expf(acc[j][2] - mx1) + __expf(acc[j][3] - mx1);
    }
    #pragma unroll
    for (int o = 1; o <= 2; o <<= 1) {
        sm0 += __shfl_xor_sync(0xffffffffu, sm0, o);
        sm1 += __shfl_xor_sync(0xffffffffu, sm1, o);
    }
    if (lw == 0) {
        sRed[(wm * 16 + r0) * 2 + wn]     = sm0;
        sRed[(wm * 16 + r0 + 8) * 2 + wn] = sm1;
    }
    __syncthreads();
    sm0 = sRed[(wm * 16 + r0) * 2]     + sRed[(wm * 16 + r0) * 2 + 1];
    sm1 = sRed[(wm * 16 + r0 + 8) * 2] + sRed[(wm * 16 + r0 + 8) * 2 + 1];
    float lse0 = mx0 + __logf(sm0);
    float lse1 = mx1 + __logf(sm1);

    float* o0 = Out + ((size_t)b * TMEL + mrow0) * TTEXT;
    float* o1 = Out + ((size_t)b * TMEL + mrow0 + 8) * TTEXT;
    #pragma unroll
    for (int j = 0; j < 25; j++) {
        int c = wn * 200 + j * 8 + lw * 2;
        *(float2*)&o0[c] = make_float2(acc[j][0] - lse0, acc[j][1] - lse0);
        *(float2*)&o1[c] = make_float2(acc[j][2] - lse1, acc[j][3] - lse1);
    }
}

// ---------------- launch ----------------
extern "C" void kernel_launch(void* const* d_in, const int* in_sizes, int n_in,
                              void* d_out, int out_size)
{
    const float* hs   = (const float*)d_in[0];
    const float* ys   = (const float*)d_in[1];
    const unsigned char* mask = (const unsigned char*)d_in[2];
    const float* t_w1 = (const float*)d_in[3];
    const float* t_b1 = (const float*)d_in[4];
    const float* t_w2 = (const float*)d_in[5];
    const float* t_b2 = (const float*)d_in[6];
    const float* m_w1 = (const float*)d_in[7];
    const float* m_b1 = (const float*)d_in[8];
    const float* m_w2 = (const float*)d_in[9];
    const float* m_b2 = (const float*)d_in[10];
    const float* m_w3 = (const float*)d_in[11];
    const float* m_b3 = (const float*)d_in[12];
    float* out = (float*)d_out;

    __half *xht, *xin, *h1h, *xhm, *y1h, *y2h;
    __half *wt1, *wt2, *wm1, *wm2, *wm3;
    float *hn, *yn;
    cudaGetSymbolAddress((void**)&xht, g_xht);
    cudaGetSymbolAddress((void**)&xin, g_xin); cudaGetSymbolAddress((void**)&h1h, g_h1h);
    cudaGetSymbolAddress((void**)&xhm, g_xhm);
    cudaGetSymbolAddress((void**)&y1h, g_y1h); cudaGetSymbolAddress((void**)&y2h, g_y2h);
    cudaGetSymbolAddress((void**)&wt1, g_wt1); cudaGetSymbolAddress((void**)&wt2, g_wt2);
    cudaGetSymbolAddress((void**)&wm1, g_wm1); cudaGetSymbolAddress((void**)&wm2, g_wm2);
    cudaGetSymbolAddress((void**)&wm3, g_wm3);
    cudaGetSymbolAddress((void**)&hn, g_hn);   cudaGetSymbolAddress((void**)&yn, g_yn);

    cudaFuncSetAttribute(convmma_k<3, 384, true >,
                         cudaFuncAttributeMaxDynamicSharedMemorySize, CONV_SMEM(3));
    cudaFuncSetAttribute(convmma_k<1, 384, false>,
                         cudaFuncAttributeMaxDynamicSharedMemorySize, CONV_SMEM(1));
    cudaFuncSetAttribute(convmma_k<3, 128, true >,
                         cudaFuncAttributeMaxDynamicSharedMemorySize, CONV_SMEM(3));
    cudaFuncSetAttribute(attnmma_k,
                         cudaFuncAttributeMaxDynamicSharedMemorySize, ATTN_SMEM);

    // #0: merged input split (fp16)
    {
        long mel = (long)BB * TMEL * CIPM;
        dim3 g((unsigned)((mel + 255) / 256), 2);
        xsplit_all_k<<<g, 256>>>(hs, ys, xin, xhm);
    }
    // #1: merged weight split (fp16)
    {
        dim3 g((3 * 384 * ADIM + 255) / 256, 5);
        wsplit_all_k<<<g, 256>>>(t_w1, t_w2, m_w1, m_w2, m_w3,
                                 wt1, wt2, wm1, wm2, wm3);
    }

    // #2-#3: text prenet
    {
        dim3 g((TTEXT + 127) / 128, 3, BB);
        convmma_k<3, 384, true ><<<g, 256, CONV_SMEM(3)>>>(
            xin, wt1, t_b1, h1h, TTEXT);
        convmma_k<1, 384, false><<<g, 256, CONV_SMEM(1)>>>(
            h1h, wt2, t_b2, xht, TTEXT);
    }
    // #4-#6: mel prenet (#5 = m-conv2, the ncu-profiled launch)
    {
        dim3 g((TMEL + 127) / 128, 3, BB);
        convmma_k<3, 128, true ><<<g, 256, CONV_SMEM(3)>>>(
            xhm, wm1, m_b1, y1h, TMEL);
        convmma_k<3, 384, true ><<<g, 256, CONV_SMEM(3)>>>(
            y1h, wm2, m_b2, y2h, TMEL);
        convmma_k<1, 384, false><<<g, 256, CONV_SMEM(1)>>>(
            y2h, wm3, m_b3, y1h, TMEL);
    }

    // row norms from the exact fp16 operands the dot uses
    rownorm2_k<<<BB * TTEXT, 128>>>(xht, hn);
    rownorm2_k<<<BB * TMEL, 128>>>(y1h, yn);

    // fused distance + log_softmax (single-term fp16 tensor-core)
    {
        dim3 g(TMEL / 64, BB);
        attnmma_k<<<g, 256, ATTN_SMEM>>>(y1h, xht, yn, hn, mask, out);
    }
}

// round 16
// speedup vs baseline: 1.9010x; 1.0965x over previous
#include <cuda_runtime.h>
#include <cuda_fp16.h>
#include <math.h>
#include <stdint.h>

#define BB    32
#define TTEXT 400
#define TMEL  1600
#define ADIM  384
#define ODIM  80
#define CIPM  128   // mel input channels padded 80 -> 128

// ---------------- static scratch (no allocations allowed) ----------------
__device__ __half g_xht[(size_t)BB * TTEXT * ADIM];   // text conv2 out (attn H)
__device__ __half g_xin[(size_t)BB * TTEXT * ADIM];   // text input
__device__ __half g_h1h[(size_t)BB * TTEXT * ADIM];
__device__ __half g_xhm[(size_t)BB * TMEL * CIPM];    // mel input (padded)
__device__ __half g_y1h[(size_t)BB * TMEL * ADIM];
__device__ __half g_y2h[(size_t)BB * TMEL * ADIM];
// weights fp16, layout [k][co][ci_padded]
__device__ __half g_wt1[3 * 384 * ADIM];
__device__ __half g_wt2[1 * 384 * ADIM];
__device__ __half g_wm1[3 * 384 * CIPM];
__device__ __half g_wm2[3 * 384 * ADIM];
__device__ __half g_wm3[1 * 384 * ADIM];
__device__ float g_hn[BB * TTEXT];
__device__ float g_yn[BB * TMEL];

// ---------------- PTX helpers (family-level only) ----------------
__device__ __forceinline__ unsigned int sm_u32(const void* p)
{
    return (unsigned int)__cvta_generic_to_shared(p);
}
__device__ __forceinline__ void cp16(unsigned int dst, const void* src,
                                     unsigned int bytes)
{
    asm volatile("cp.async.cg.shared.global [%0], [%1], 16, %2;"
                 :: "r"(dst), "l"(src), "r"(bytes) : "memory");
}
__device__ __forceinline__ void cp_commit()
{
    asm volatile("cp.async.commit_group;" ::: "memory");
}
template<int N>
__device__ __forceinline__ void cp_wait()
{
    asm volatile("cp.async.wait_group %0;" :: "n"(N) : "memory");
}
__device__ __forceinline__ void ldsm4(unsigned int* r, unsigned int addr)
{
    asm volatile("ldmatrix.sync.aligned.m8n8.x4.shared.b16 {%0,%1,%2,%3}, [%4];"
                 : "=r"(r[0]), "=r"(r[1]), "=r"(r[2]), "=r"(r[3]) : "r"(addr));
}
__device__ __forceinline__ void mma16816(float* c, const unsigned int* a,
                                         const unsigned int* b)
{
    asm volatile("mma.sync.aligned.m16n8k16.row.col.f32.f16.f16.f32 "
                 "{%0,%1,%2,%3}, {%4,%5,%6,%7}, {%8,%9}, {%0,%1,%2,%3};"
                 : "+f"(c[0]), "+f"(c[1]), "+f"(c[2]), "+f"(c[3])
                 : "r"(a[0]), "r"(a[1]), "r"(a[2]), "r"(a[3]),
                   "r"(b[0]), "r"(b[1]));
}
__device__ __forceinline__ unsigned int sw64(unsigned int bo)
{
    return bo ^ ((bo >> 3) & 0x30);
}

// ---------------- merged input split: fp16 ----------------
__global__ void xsplit_all_k(const float* __restrict__ hs, const float* __restrict__ ys,
                             __half* __restrict__ xin, __half* __restrict__ xhm)
{
    long idx = (long)blockIdx.x * 256 + threadIdx.x;
    if (blockIdx.y == 0) {
        long total = (long)BB * TTEXT * ADIM;
        if (idx >= total) return;
        xin[idx] = __float2half(hs[idx]);
    } else {
        long total = (long)BB * TMEL * CIPM;
        if (idx >= total) return;
        long r = idx >> 7;
        int  c = (int)(idx & 127);
        xhm[idx] = __float2half((c < ODIM) ? ys[r * ODIM + c] : 0.f);
    }
}

// ---------------- merged weight split: all 5 tensors, single fp16 ---------------
__device__ __forceinline__ void wsplit_one(const float* W, __half* Wh,
                                           int CIN, int CIP, int KS, int idx)
{
    int total = KS * 384 * CIP;
    if (idx >= total) return;
    int k   = idx / (384 * CIP);
    int rem = idx - k * 384 * CIP;
    int co  = rem / CIP;
    int ci  = rem - co * CIP;
    float v = (ci < CIN) ? W[((size_t)co * CIN + ci) * KS + k] : 0.f;
    Wh[idx] = __float2half(v);
}

__global__ void wsplit_all_k(const float* tw1, const float* tw2, const float* mw1,
                             const float* mw2, const float* mw3,
                             __half* wt1, __half* wt2, __half* wm1,
                             __half* wm2, __half* wm3)
{
    int idx = blockIdx.x * 256 + threadIdx.x;
    switch (blockIdx.y) {
    case 0: wsplit_one(tw1, wt1, ADIM, ADIM, 3, idx); break;
    case 1: wsplit_one(tw2, wt2, ADIM, ADIM, 1, idx); break;
    case 2: wsplit_one(mw1, wm1, ODIM, CIPM, 3, idx); break;
    case 3: wsplit_one(mw2, wm2, ADIM, ADIM, 3, idx); break;
    case 4: wsplit_one(mw3, wm3, ADIM, ADIM, 1, idx); break;
    }
}

// ---------------- conv1d via single-term fp16 mma.sync, TAP-FUSED ---------------
// CTA tile: 128 time-rows x 128 couts, 8 warps, warp tile 64x32 (wm 2 x wn 4).
// Optional fused row-norm (atomicAdd per row) for the final layers.
template<int KS> struct ConvCfg;
template<> struct ConvCfg<3> { static const int ARB = 8448; };  // 130 rows + pad
template<> struct ConvCfg<1> { static const int ARB = 8192; };  // 128 rows
#define CONV_STAGE(KS)  (ConvCfg<KS>::ARB + KS * 8192)
#define CONV_SMEM(KS)   (1024 + 3 * CONV_STAGE(KS))

template<int KS, int CIP, bool RELU, bool NORM>
__global__ __launch_bounds__(256, 2)
void convmma_k(const __half* __restrict__ Xh, const __half* __restrict__ Wh,
               const float* __restrict__ bias, __half* __restrict__ Oh,
               float* __restrict__ Nrm, int T)
{
    constexpr int PAD   = (KS - 1) / 2;
    constexpr int NS    = CIP / 32;
    constexpr int AR    = 128 + KS - 1;
    constexpr int ARB   = ConvCfg<KS>::ARB;
    constexpr int STAGE = ARB + KS * 8192;
    extern __shared__ char smem[];
    const unsigned int su = sm_u32(smem);

    const int tid  = threadIdx.x;
    const int lane = tid & 31;
    const int wid  = tid >> 5;
    const int wm   = wid & 1;
    const int wn   = wid >> 1;
    const int b    = blockIdx.z;
    const int t0   = blockIdx.x * 128;
    const int n0   = blockIdx.y * 128;

    float* sBias = (float*)smem;
    if (tid < 128) sBias[tid] = bias[n0 + tid];

    const int g  = lane >> 3, wi = lane & 7;
    const int arow = ((g & 1) << 3) + wi, acg = g >> 1;
    const int brow = ((g >> 1) << 3) + wi, bcg = g & 1;

    auto fill = [&](int step) {
        int ch = step;
        unsigned int st = su + 1024 + (step % 3) * STAGE;
        #pragma unroll
        for (int i = tid; i < AR * 4; i += 256) {
            int r = i >> 2, c = i & 3;
            unsigned int sw = sw64(r * 64 + c * 16);
            int t  = t0 + r - PAD;
            int tc = t < 0 ? 0 : (t >= T ? T - 1 : t);
            unsigned int ok = (t >= 0 && t < T) ? 16u : 0u;
            size_t src = ((size_t)b * T + tc) * CIP + ch * 32 + c * 8;
            cp16(st + sw, Xh + src, ok);
        }
        #pragma unroll
        for (int i = tid; i < KS * 512; i += 256) {
            int tap = i >> 9;
            int rem = i & 511;
            int r = rem >> 2, c = rem & 3;
            unsigned int dst = st + ARB + tap * 8192 + sw64(r * 64 + c * 16);
            size_t src = ((size_t)tap * 384 + n0 + r) * CIP + ch * 32 + c * 8;
            cp16(dst, Wh + src, 16u);
        }
        cp_commit();
    };

    float acc[4][4][4];
    #pragma unroll
    for (int i = 0; i < 4; i++)
        #pragma unroll
        for (int j = 0; j < 4; j++)
            #pragma unroll
            for (int e = 0; e < 4; e++) acc[i][j][e] = 0.f;

    fill(0);
    if (NS > 1) fill(1);
    for (int step = 0; step < NS; step++) {
        if (step == NS - 1) cp_wait<0>();
        else                cp_wait<1>();
        __syncthreads();
        if (step + 2 < NS) fill(step + 2);

        unsigned int st = su + 1024 + (step % 3) * STAGE;
        #pragma unroll
        for (int k = 0; k < KS; k++) {
            unsigned int bb = st + ARB + k * 8192;
            #pragma unroll
            for (int kq = 0; kq < 2; kq++) {
                unsigned int a_h[4][4], b_h[2][4];
                #pragma unroll
                for (int i = 0; i < 4; i++) {
                    unsigned int bo = sw64((wm * 64 + i * 16 + arow + k) * 64
                                           + (kq * 2 + acg) * 16);
                    ldsm4(a_h[i], st + bo);
                }
                #pragma unroll
                for (int p = 0; p < 2; p++) {
                    unsigned int bo = sw64((wn * 32 + p * 16 + brow) * 64
                                           + (kq * 2 + bcg) * 16);
                    ldsm4(b_h[p], bb + bo);
                }
                #pragma unroll
                for (int i = 0; i < 4; i++)
                    #pragma unroll
                    for (int j = 0; j < 4; j++)
                        mma16816(acc[i][j], a_h[i], &b_h[j >> 1][(j & 1) * 2]);
            }
        }
    }

    #pragma unroll
    for (int i = 0; i < 4; i++) {
        #pragma unroll
        for (int half = 0; half < 2; half++) {
            int t = t0 + wm * 64 + i * 16 + (lane >> 2) + half * 8;
            bool valid = (t < T);
            float rsum = 0.f;
            if (valid) {
                size_t base = ((size_t)b * T + t) * 384 + n0;
                #pragma unroll
                for (int j = 0; j < 4; j++) {
                    int c = wn * 32 + j * 8 + (lane & 3) * 2;
                    float v0 = acc[i][j][half * 2]     + sBias[c];
                    float v1 = acc[i][j][half * 2 + 1] + sBias[c + 1];
                    if (RELU) { v0 = fmaxf(v0, 0.f); v1 = fmaxf(v1, 0.f); }
                    __half2 hp;
                    hp.x = __float2half(v0); hp.y = __float2half(v1);
                    *(__half2*)&Oh[base + c] = hp;
                    if (NORM) {
                        float q0 = __half2float(hp.x);
                        float q1 = __half2float(hp.y);
                        rsum += q0 * q0 + q1 * q1;
                    }
                }
            }
            if (NORM) {
                rsum += __shfl_xor_sync(0xffffffffu, rsum, 1);
                rsum += __shfl_xor_sync(0xffffffffu, rsum, 2);
                if (valid && (lane & 3) == 0)
                    atomicAdd(&Nrm[(size_t)b * T + t], rsum);
            }
        }
    }
}

// ---------------- fused distance mma-GEMM + sqrt + mask + log_softmax --------
// ldmatrix path: Y and H staged in sw64 64B-pitch rows.
// H padded: each 200-col half padded to 208 (13 n16 tiles); pad cols zfilled,
// their products land in a dummy accumulator (never read).
#define ATTN_HDR   2112
#define ATTN_STAGE 30720            // Y 4096 + H 416*64
#define ATTN_SMEM  (ATTN_HDR + 2 * ATTN_STAGE)
__global__ __launch_bounds__(256)
void attnmma_k(const __half* __restrict__ Yh, const __half* __restrict__ Hh,
               const float* __restrict__ Yn, const float* __restrict__ Hn,
               const unsigned char* __restrict__ mask, float* __restrict__ Out)
{
    constexpr int NSTEP = ADIM / 32;   // 12
    extern __shared__ char smem[];
    float* sHnM = (float*)smem;                 // [400]
    float* sRed = (float*)(smem + 1600);
    const unsigned int su = sm_u32(smem);

    const int tid  = threadIdx.x;
    const int lane = tid & 31;
    const int wid  = tid >> 5;
    const int wm   = wid & 3;       // 4 groups of 16 mel rows
    const int wn   = wid >> 2;      // 2 halves of 200 text cols
    const int b    = blockIdx.y;
    const int m0   = blockIdx.x * 64;

    for (int i = tid; i < 400; i += 256)
        sHnM[i] = mask[b * TTEXT + i] ? __int_as_float(0x7f800000) : Hn[b * TTEXT + i];

    const int g  = lane >> 3, wi = lane & 7;
    const int arow = ((g & 1) << 3) + wi, acg = g >> 1;
    const int brow = ((g >> 1) << 3) + wi, bcg = g & 1;

    auto fill = [&](int step) {
        int kc = step * 32;
        unsigned int st = su + ATTN_HDR + (step & 1) * ATTN_STAGE;
        // Y: 64 rows x 4 chunks
        {
            int r = tid >> 2, q = tid & 3;
            unsigned int dst = st + sw64(r * 64 + q * 16);
            size_t src = ((size_t)b * TMEL + m0 + r) * ADIM + kc + q * 8;
            cp16(dst, Yh + src, 16u);
        }
        // H: 416 padded rows x 4 chunks (halves of 208; local>=200 zfilled)
        #pragma unroll 2
        for (int i = tid; i < 1664; i += 256) {
            int rr = i >> 2, q = i & 3;
            int half  = rr >= 208;
            int local = rr - half * 208;
            int n = half * 200 + local;
            unsigned int ok = (local < 200) ? 16u : 0u;
            int nc = n < TTEXT ? n : TTEXT - 1;
            unsigned int dst = st + 4096 + sw64(rr * 64 + q * 16);
            size_t src = ((size_t)b * TTEXT + nc) * ADIM + kc + q * 8;
            cp16(dst, Hh + src, 16u);
        }
        cp_commit();
    };

    float acc[25][4];
    float accd[4];                  // dummy for padded n8
    #pragma unroll
    for (int j = 0; j < 25; j++)
        #pragma unroll
        for (int e = 0; e < 4; e++) acc[j][e] = 0.f;
    #pragma unroll
    for (int e = 0; e < 4; e++) accd[e] = 0.f;

    fill(0);
    for (int step = 0; step < NSTEP; step++) {
        if (step + 1 < NSTEP) { fill(step + 1); cp_wait<1>(); }
        else                  { cp_wait<0>(); }
        __syncthreads();

        unsigned int st = su + ATTN_HDR + (step & 1) * ATTN_STAGE;
        #pragma unroll
        for (int kq = 0; kq < 2; kq++) {
            unsigned int a[4];
            ldsm4(a, st + sw64((wm * 16 + arow) * 64 + (kq * 2 + acg) * 16));
            #pragma unroll
            for (int jt = 0; jt < 13; jt++) {
                unsigned int bf[4];
                ldsm4(bf, st + 4096 + sw64((wn * 208 + jt * 16 + brow) * 64
                                           + (kq * 2 + bcg) * 16));
                mma16816(acc[2 * jt], a, &bf[0]);
                if (jt < 12) mma16816(acc[2 * jt + 1], a, &bf[2]);
                else         mma16816(accd,            a, &bf[2]);
            }
        }
        __syncthreads();
    }

    const int r0 = lane >> 2;
    const int lw = lane & 3;
    int mrow0 = m0 + wm * 16 + r0;
    float yn0 = Yn[b * TMEL + mrow0];
    float yn1 = Yn[b * TMEL + mrow0 + 8];

    #pragma unroll
    for (int j = 0; j < 25; j++) {
        int c = wn * 200 + j * 8 + lw * 2;
        float hn0 = sHnM[c], hn1 = sHnM[c + 1];
        acc[j][0] = -sqrtf(fmaxf(yn0 + hn0 - 2.f * acc[j][0], 1e-12f));
        acc[j][1] = -sqrtf(fmaxf(yn0 + hn1 - 2.f * acc[j][1], 1e-12f));
        acc[j][2] = -sqrtf(fmaxf(yn1 + hn0 - 2.f * acc[j][2], 1e-12f));
        acc[j][3] = -sqrtf(fmaxf(yn1 + hn1 - 2.f * acc[j][3], 1e-12f));
    }

    float mx0 = -INFINITY, mx1 = -INFINITY;
    #pragma unroll
    for (int j = 0; j < 25; j++) {
        mx0 = fmaxf(mx0, fmaxf(acc[j][0], acc[j][1]));
        mx1 = fmaxf(mx1, fmaxf(acc[j][2], acc[j][3]));
    }
    #pragma unroll
    for (int o = 1; o <= 2; o <<= 1) {
        mx0 = fmaxf(mx0, __shfl_xor_sync(0xffffffffu, mx0, o));
        mx1 = fmaxf(mx1, __shfl_xor_sync(0xffffffffu, mx1, o));
    }
    if (lw == 0) {
        sRed[(wm * 16 + r0) * 2 + wn]     = mx0;
        sRed[(wm * 16 + r0 + 8) * 2 + wn] = mx1;
    }
    __syncthreads();
    mx0 = fmaxf(sRed[(wm * 16 + r0) * 2],     sRed[(wm * 16 + r0) * 2 + 1]);
    mx1 = fmaxf(sRed[(wm * 16 + r0 + 8) * 2], sRed[(wm * 16 + r0 + 8) * 2 + 1]);
    __syncthreads();

    float sm0 = 0.f, sm1 = 0.f;
    #pragma unroll
    for (int j = 0; j < 25; j++) {
        sm0 += __expf(acc[j][0] - mx0) + __expf(acc[j][1] - mx0);
        sm1 += __expf(acc[j][2] - mx1) + __expf(acc[j][3] - mx1);
    }
    #pragma unroll
    for (int o = 1; o <= 2; o <<= 1) {
        sm0 += __shfl_xor_sync(0xffffffffu, sm0, o);
        sm1 += __shfl_xor_sync(0xffffffffu, sm1, o);
    }
    if (lw == 0) {
        sRed[(wm * 16 + r0) * 2 + wn]     = sm0;
        sRed[(wm * 16 + r0 + 8) * 2 + wn] = sm1;
    }
    __syncthreads();
    sm0 = sRed[(wm * 16 + r0) * 2]     + sRed[(wm * 16 + r0) * 2 + 1];
    sm1 = sRed[(wm * 16 + r0 + 8) * 2] + sRed[(wm * 16 + r0 + 8) * 2 + 1];
    float lse0 = mx0 + __logf(sm0);
    float lse1 = mx1 + __logf(sm1);

    float* o0 = Out + ((size_t)b * TMEL + mrow0) * TTEXT;
    float* o1 = Out + ((size_t)b * TMEL + mrow0 + 8) * TTEXT;
    #pragma unroll
    for (int j = 0; j < 25; j++) {
        int c = wn * 200 + j * 8 + lw * 2;
        *(float2*)&o0[c] = make_float2(acc[j][0] - lse0, acc[j][1] - lse0);
        *(float2*)&o1[c] = make_float2(acc[j][2] - lse1, acc[j][3] - lse1);
    }
}

// ---------------- launch ----------------
extern "C" void kernel_launch(void* const* d_in, const int* in_sizes, int n_in,
                              void* d_out, int out_size)
{
    const float* hs   = (const float*)d_in[0];
    const float* ys   = (const float*)d_in[1];
    const unsigned char* mask = (const unsigned char*)d_in[2];
    const float* t_w1 = (const float*)d_in[3];
    const float* t_b1 = (const float*)d_in[4];
    const float* t_w2 = (const float*)d_in[5];
    const float* t_b2 = (const float*)d_in[6];
    const float* m_w1 = (const float*)d_in[7];
    const float* m_b1 = (const float*)d_in[8];
    const float* m_w2 = (const float*)d_in[9];
    const float* m_b2 = (const float*)d_in[10];
    const float* m_w3 = (const float*)d_in[11];
    const float* m_b3 = (const float*)d_in[12];
    float* out = (float*)d_out;

    __half *xht, *xin, *h1h, *xhm, *y1h, *y2h;
    __half *wt1, *wt2, *wm1, *wm2, *wm3;
    float *hn, *yn;
    cudaGetSymbolAddress((void**)&xht, g_xht);
    cudaGetSymbolAddress((void**)&xin, g_xin); cudaGetSymbolAddress((void**)&h1h, g_h1h);
    cudaGetSymbolAddress((void**)&xhm, g_xhm);
    cudaGetSymbolAddress((void**)&y1h, g_y1h); cudaGetSymbolAddress((void**)&y2h, g_y2h);
    cudaGetSymbolAddress((void**)&wt1, g_wt1); cudaGetSymbolAddress((void**)&wt2, g_wt2);
    cudaGetSymbolAddress((void**)&wm1, g_wm1); cudaGetSymbolAddress((void**)&wm2, g_wm2);
    cudaGetSymbolAddress((void**)&wm3, g_wm3);
    cudaGetSymbolAddress((void**)&hn, g_hn);   cudaGetSymbolAddress((void**)&yn, g_yn);

    cudaFuncSetAttribute(convmma_k<3, 384, true,  false>,
                         cudaFuncAttributeMaxDynamicSharedMemorySize, CONV_SMEM(3));
    cudaFuncSetAttribute(convmma_k<1, 384, false, true >,
                         cudaFuncAttributeMaxDynamicSharedMemorySize, CONV_SMEM(1));
    cudaFuncSetAttribute(convmma_k<3, 128, true,  false>,
                         cudaFuncAttributeMaxDynamicSharedMemorySize, CONV_SMEM(3));
    cudaFuncSetAttribute(attnmma_k,
                         cudaFuncAttributeMaxDynamicSharedMemorySize, ATTN_SMEM);

    // zero norm accumulators (fused epilogues atomicAdd into them)
    cudaMemsetAsync(hn, 0, (size_t)BB * TTEXT * sizeof(float));
    cudaMemsetAsync(yn, 0, (size_t)BB * TMEL * sizeof(float));

    // merged input split (fp16)
    {
        long mel = (long)BB * TMEL * CIPM;
        dim3 g((unsigned)((mel + 255) / 256), 2);
        xsplit_all_k<<<g, 256>>>(hs, ys, xin, xhm);
    }
    // merged weight split (fp16)
    {
        dim3 g((3 * 384 * ADIM + 255) / 256, 5);
        wsplit_all_k<<<g, 256>>>(t_w1, t_w2, m_w1, m_w2, m_w3,
                                 wt1, wt2, wm1, wm2, wm3);
    }

    // text prenet (conv2 fuses H row-norms)
    {
        dim3 g((TTEXT + 127) / 128, 3, BB);
        convmma_k<3, 384, true,  false><<<g, 256, CONV_SMEM(3)>>>(
            xin, wt1, t_b1, h1h, nullptr, TTEXT);
        convmma_k<1, 384, false, true ><<<g, 256, CONV_SMEM(1)>>>(
            h1h, wt2, t_b2, xht, hn, TTEXT);
    }
    // mel prenet (conv3 fuses Y row-norms)
    {
        dim3 g((TMEL + 127) / 128, 3, BB);
        convmma_k<3, 128, true,  false><<<g, 256, CONV_SMEM(3)>>>(
            xhm, wm1, m_b1, y1h, nullptr, TMEL);
        convmma_k<3, 384, true,  false><<<g, 256, CONV_SMEM(3)>>>(
            y1h, wm2, m_b2, y2h, nullptr, TMEL);
        convmma_k<1, 384, false, true ><<<g, 256, CONV_SMEM(1)>>>(
            y2h, wm3, m_b3, y1h, yn, TMEL);
    }

    // fused distance + log_softmax (ldmatrix fp16 tensor-core)
    {
        dim3 g(TMEL / 64, BB);
        attnmma_k<<<g, 256, ATTN_SMEM>>>(y1h, xht, yn, hn, mask, out);
    }
}